// round 1
// baseline (speedup 1.0000x reference)
#include <cuda_runtime.h>
#include <cuda_bf16.h>

// ---------------- problem constants ----------------
#define N_NODES   50000
#define N_EDGES   800000
#define N_GRAPHS  64
#define IN_DIM    128
#define HID       256
#define N_LAYERS  4
#define NPAD      50016   // 32*1563, padded row count for GEMM tiling

// ---------------- device scratch (no allocations allowed) ----------------
__device__ float g_x[(size_t)NPAD * HID];     // node features (updated per layer)
__device__ float g_c[(size_t)NPAD * HID];     // aggregated neighbor means
__device__ int   g_deg[N_NODES];
__device__ int   g_rowoff[N_NODES + 1];
__device__ int   g_cursor[N_NODES];
__device__ int   g_csr[N_EDGES];
__device__ float g_inv[N_NODES];
__device__ float g_hg[N_GRAPHS * HID];
__device__ float g_gcnt[N_GRAPHS];

// ---------------- f32x2 packed-FMA helpers ----------------
__device__ __forceinline__ unsigned long long dup2(float x) {
    unsigned long long r;
    asm("mov.b64 %0, {%1, %1};" : "=l"(r) : "f"(x));
    return r;
}
__device__ __forceinline__ void fma2(unsigned long long& d,
                                     unsigned long long a,
                                     unsigned long long b) {
    asm("fma.rn.f32x2 %0, %1, %2, %3;" : "=l"(d) : "l"(a), "l"(b), "l"(d));
}
__device__ __forceinline__ float2 unpk2(unsigned long long v) {
    float2 r;
    asm("mov.b64 {%0, %1}, %2;" : "=f"(r.x), "=f"(r.y) : "l"(v));
    return r;
}

// ---------------- init: zero degree + graph accumulators ----------------
__global__ void init_k() {
    int i = blockIdx.x * blockDim.x + threadIdx.x;
    if (i < N_NODES) g_deg[i] = 0;
    if (i < N_GRAPHS * HID) g_hg[i] = 0.0f;
    if (i < N_GRAPHS) g_gcnt[i] = 0.0f;
}

// ---------------- CSR build ----------------
__global__ void deg_k(const int* __restrict__ dst) {
    int i = blockIdx.x * blockDim.x + threadIdx.x;
    if (i < N_EDGES) atomicAdd(&g_deg[dst[i]], 1);
}

__global__ void scan_k() {
    __shared__ int sh[1024];
    __shared__ int base_s;
    int tid = threadIdx.x;
    if (tid == 0) base_s = 0;
    __syncthreads();
    for (int start = 0; start < N_NODES; start += 1024) {
        int i = start + tid;
        int v = (i < N_NODES) ? g_deg[i] : 0;
        sh[tid] = v;
        __syncthreads();
        for (int off = 1; off < 1024; off <<= 1) {
            int t = (tid >= off) ? sh[tid - off] : 0;
            __syncthreads();
            sh[tid] += t;
            __syncthreads();
        }
        int incl = sh[tid];
        int total = sh[1023];
        int base = base_s;
        if (i < N_NODES) {
            int ro = base + incl - v;
            g_rowoff[i] = ro;
            g_cursor[i] = ro;
            g_inv[i] = 1.0f / (float)(v > 0 ? v : 1);
        }
        __syncthreads();
        if (tid == 0) base_s = base + total;
        __syncthreads();
    }
    if (tid == 0) g_rowoff[N_NODES] = base_s;
}

__global__ void fill_k(const int* __restrict__ src, const int* __restrict__ dst) {
    int i = blockIdx.x * blockDim.x + threadIdx.x;
    if (i < N_EDGES) {
        int d = dst[i];
        int p = atomicAdd(&g_cursor[d], 1);
        g_csr[p] = src[i];
    }
}

// ---------------- per-layer mean aggregation: c[n] = mean_{e: dst=n} x[src[e]] ----
__global__ void __launch_bounds__(256) agg_k() {
    int gw = (blockIdx.x * blockDim.x + threadIdx.x) >> 5;
    int lane = threadIdx.x & 31;
    if (gw >= N_NODES) return;
    int beg = g_rowoff[gw];
    int end = g_rowoff[gw + 1];
    float4 s0 = make_float4(0.f, 0.f, 0.f, 0.f);
    float4 s1 = make_float4(0.f, 0.f, 0.f, 0.f);
    #pragma unroll 2
    for (int j = beg; j < end; j++) {
        int s = g_csr[j];
        const float4* xr = (const float4*)(g_x + (size_t)s * HID);
        float4 a = xr[lane];
        float4 b = xr[lane + 32];
        s0.x += a.x; s0.y += a.y; s0.z += a.z; s0.w += a.w;
        s1.x += b.x; s1.y += b.y; s1.z += b.z; s1.w += b.w;
    }
    float inv = g_inv[gw];
    s0.x *= inv; s0.y *= inv; s0.z *= inv; s0.w *= inv;
    s1.x *= inv; s1.y *= inv; s1.z *= inv; s1.w *= inv;
    float4* cr = (float4*)(g_c + (size_t)gw * HID);
    cr[lane] = s0;
    cr[lane + 32] = s1;
}

// ---------------- fused GEMM (+ epilogue) ----------------
// MODE 0: g_x = h(ext,[N,128]) @ W([128,256]) + bias
// MODE 1: bundle = [g_x | g_c]([N,512]) @ W([512,256]) + bias;
//         g_x += relu(bundle / max(||bundle||_2, 1e-12))  (rowwise norm)
// Block: 256 threads, tile BM=32 rows x BN=256 cols, BK=16.
template <int MODE>
__global__ void __launch_bounds__(256) gemm_k(const float* __restrict__ A0ext,
                                              const float* __restrict__ W,
                                              const float* __restrict__ bias) {
    const int K   = (MODE == 0) ? IN_DIM : 2 * HID;
    const int lda = (MODE == 0) ? IN_DIM : HID;

    __shared__ float As[16][34];     // padded: conflict-free STS, 8B-aligned rows
    __shared__ float Bs[16][256];
    __shared__ float ssq_s[8][8];

    int tid = threadIdx.x;
    int ty = tid >> 6;       // 0..3  -> row group (8 rows)
    int tx = tid & 63;       // 0..63 -> col group (4 cols)
    int row0 = blockIdx.x * 32;

    int arow = tid >> 3;           // 0..31
    int akk  = (tid & 7) * 2;      // 0,2,...,14

    unsigned long long acc[4][4];
    #pragma unroll
    for (int i = 0; i < 4; i++)
        #pragma unroll
        for (int j = 0; j < 4; j++) acc[i][j] = 0ULL;

    for (int kb = 0; kb < K; kb += 16) {
        // --- load A tile (32 rows x 16 k), stored transposed ---
        const float* Asrc;
        int kcol;
        if (MODE == 0) {
            Asrc = A0ext;
            kcol = kb + akk;
        } else {
            Asrc = (kb < HID) ? g_x : g_c;
            kcol = ((kb < HID) ? kb : (kb - HID)) + akk;
        }
        int gr = row0 + arow;
        float2 av;
        if (MODE == 0 && gr >= N_NODES) {
            av = make_float2(0.f, 0.f);
        } else {
            av = *(const float2*)(Asrc + (size_t)gr * lda + kcol);
        }
        As[akk][arow] = av.x;
        As[akk + 1][arow] = av.y;

        // --- load B tile (16 k x 256 n) ---
        #pragma unroll
        for (int r = 0; r < 4; r++) {
            int k = r * 4 + (tid >> 6);
            int n4 = tid & 63;
            *(float4*)&Bs[k][n4 * 4] =
                *(const float4*)(W + (size_t)(kb + k) * 256 + n4 * 4);
        }
        __syncthreads();

        // --- compute: 16 k-steps, f32x2 packed FMAs (rows paired) ---
        #pragma unroll
        for (int k = 0; k < 16; k++) {
            float4 b = *(const float4*)&Bs[k][tx * 4];
            unsigned long long b2[4];
            b2[0] = dup2(b.x); b2[1] = dup2(b.y);
            b2[2] = dup2(b.z); b2[3] = dup2(b.w);
            #pragma unroll
            for (int i = 0; i < 4; i++) {
                unsigned long long a2 =
                    *(const unsigned long long*)&As[k][ty * 8 + 2 * i];
                #pragma unroll
                for (int j = 0; j < 4; j++) fma2(acc[i][j], a2, b2[j]);
            }
        }
        __syncthreads();
    }

    // --- epilogue ---
    float4 bv = *(const float4*)(bias + tx * 4);
    float bb[4] = {bv.x, bv.y, bv.z, bv.w};
    float vv[8][4];
    #pragma unroll
    for (int i = 0; i < 4; i++) {
        #pragma unroll
        for (int j = 0; j < 4; j++) {
            float2 p = unpk2(acc[i][j]);
            vv[2 * i][j] = p.x + bb[j];
            vv[2 * i + 1][j] = p.y + bb[j];
        }
    }

    if (MODE == 0) {
        #pragma unroll
        for (int i = 0; i < 8; i++) {
            int row = row0 + ty * 8 + i;
            float4 o = make_float4(vv[i][0], vv[i][1], vv[i][2], vv[i][3]);
            *(float4*)&g_x[(size_t)row * HID + tx * 4] = o;
        }
    } else {
        // rowwise sum of squares: reduce over 64 col-threads (2 warps per row group)
        float srow[8];
        #pragma unroll
        for (int i = 0; i < 8; i++) {
            float s = vv[i][0] * vv[i][0] + vv[i][1] * vv[i][1] +
                      vv[i][2] * vv[i][2] + vv[i][3] * vv[i][3];
            #pragma unroll
            for (int off = 16; off > 0; off >>= 1)
                s += __shfl_xor_sync(0xffffffffu, s, off);
            srow[i] = s;
        }
        int warp = tid >> 5;
        if ((tid & 31) == 0) {
            #pragma unroll
            for (int i = 0; i < 8; i++) ssq_s[warp][i] = srow[i];
        }
        __syncthreads();
        #pragma unroll
        for (int i = 0; i < 8; i++) {
            float ns = ssq_s[2 * ty][i] + ssq_s[2 * ty + 1][i];
            float invn = 1.0f / fmaxf(sqrtf(ns), 1e-12f);
            int row = row0 + ty * 8 + i;
            float4* xp = (float4*)&g_x[(size_t)row * HID + tx * 4];
            float4 xo = *xp;
            xo.x += fmaxf(vv[i][0], 0.0f) * invn;
            xo.y += fmaxf(vv[i][1], 0.0f) * invn;
            xo.z += fmaxf(vv[i][2], 0.0f) * invn;
            xo.w += fmaxf(vv[i][3], 0.0f) * invn;
            *xp = xo;
        }
    }
}

// ---------------- graph mean pool accumulation ----------------
__global__ void accum_k(const int* __restrict__ gid) {
    int n = blockIdx.x;        // one block per node
    int c = threadIdx.x;       // 256 cols
    int g = gid[n];
    atomicAdd(&g_hg[g * HID + c], g_x[(size_t)n * HID + c]);
    if (c == 0) atomicAdd(&g_gcnt[g], 1.0f);
}

// ---------------- readout: prototype distances -> fc -> sigmoid ----------------
__global__ void final_k(const float* __restrict__ p_pos,
                        const float* __restrict__ p_neg,
                        const float* __restrict__ W_fc,
                        float* __restrict__ out) {
    __shared__ float ss[N_GRAPHS][10];
    int t = threadIdx.x;
    if (t < N_GRAPHS * 10) {
        int g = t / 10;
        int p = t % 10;
        const float* P = (p < 5) ? (p_pos + p * HID) : (p_neg + (p - 5) * HID);
        float invc = 1.0f / fmaxf(g_gcnt[g], 1.0f);
        float d = 0.0f;
        for (int c = 0; c < HID; c++) {
            float diff = g_hg[g * HID + c] * invc - P[c];
            d += diff * diff;
        }
        ss[g][p] = logf((d + 1.0f) / (d + 1e-12f));
    }
    __syncthreads();
    if (t < N_GRAPHS) {
        float y = 0.0f;
        #pragma unroll
        for (int j = 0; j < 10; j++) y += ss[t][j] * W_fc[j];
        out[t] = 1.0f / (1.0f + expf(-y));
    }
}

// ---------------- launch ----------------
extern "C" void kernel_launch(void* const* d_in, const int* in_sizes, int n_in,
                              void* d_out, int out_size) {
    const float* h      = (const float*)d_in[0];
    const int*   src    = (const int*)d_in[1];
    const int*   dst    = (const int*)d_in[2];
    const int*   gid    = (const int*)d_in[3];
    const float* W_emb  = (const float*)d_in[4];
    const float* b_emb  = (const float*)d_in[5];
    const float* Ws     = (const float*)d_in[6];
    const float* bs     = (const float*)d_in[7];
    const float* p_pos  = (const float*)d_in[8];
    const float* p_neg  = (const float*)d_in[9];
    const float* W_fc   = (const float*)d_in[10];
    float* out = (float*)d_out;

    init_k<<<(N_NODES + 255) / 256, 256>>>();
    deg_k<<<(N_EDGES + 255) / 256, 256>>>(dst);
    scan_k<<<1, 1024>>>();
    fill_k<<<(N_EDGES + 255) / 256, 256>>>(src, dst);

    gemm_k<0><<<NPAD / 32, 256>>>(h, W_emb, b_emb);

    for (int l = 0; l < N_LAYERS; l++) {
        agg_k<<<(N_NODES * 32 + 255) / 256, 256>>>();
        gemm_k<1><<<NPAD / 32, 256>>>(nullptr,
                                      Ws + (size_t)l * 2 * HID * HID,
                                      bs + (size_t)l * HID);
    }

    accum_k<<<N_NODES, 256>>>(gid);
    final_k<<<1, 640>>>(p_pos, p_neg, W_fc, out);
}

// round 3
// speedup vs baseline: 1.5695x; 1.5695x over previous
#include <cuda_runtime.h>
#include <cuda_bf16.h>
#include <cstdint>

// ---------------- problem constants ----------------
#define N_NODES   50000
#define N_EDGES   800000
#define N_GRAPHS  64
#define IN_DIM    128
#define HID       256
#define N_LAYERS  4
#define NPAD      50048   // 64*782
#define MT64      782

// fragment-ordered weight arrays (u32 slots, each = bf16x2)
// emb: ktiles=8, ntiles=32 ; layer: ktiles=32, ntiles=32
#define EMB_U32   (8*32*32*2)
#define LYR_U32   (32*32*32*2)
#define WF_U32    (EMB_U32 + 4*LYR_U32)

// ---------------- device scratch ----------------
__device__ float    g_x0[(size_t)NPAD * HID];
__device__ float    g_x1[(size_t)NPAD * HID];
__device__ float    g_c[(size_t)NPAD * HID];
__device__ uint32_t g_wfh[WF_U32];
__device__ uint32_t g_wfl[WF_U32];
__device__ int      g_deg[N_NODES];
__device__ int      g_rowoff[N_NODES + 1];
__device__ int      g_cursor[N_NODES];
__device__ int      g_csr[N_EDGES];
__device__ float    g_inv[N_NODES];
__device__ float    g_hg[N_GRAPHS * HID];
__device__ float    g_gcnt[N_GRAPHS];

// ---------------- helpers ----------------
// split float2 -> bf16x2 hi (rn) + bf16x2 lo (rn of residual)
__device__ __forceinline__ void split2(float2 v, uint32_t& h, uint32_t& l) {
    uint32_t hp;
    asm("cvt.rn.bf16x2.f32 %0, %1, %2;" : "=r"(hp) : "f"(v.y), "f"(v.x));
    float h0 = __uint_as_float(hp << 16);
    float h1 = __uint_as_float(hp & 0xffff0000u);
    float l0 = v.x - h0;
    float l1 = v.y - h1;
    uint32_t lp;
    asm("cvt.rn.bf16x2.f32 %0, %1, %2;" : "=r"(lp) : "f"(l1), "f"(l0));
    h = hp; l = lp;
}

__device__ __forceinline__ void mma16816(float* c, const uint32_t* a,
                                         uint32_t b0, uint32_t b1) {
    asm volatile(
        "mma.sync.aligned.m16n8k16.row.col.f32.bf16.bf16.f32 "
        "{%0,%1,%2,%3}, {%4,%5,%6,%7}, {%8,%9}, {%0,%1,%2,%3};"
        : "+f"(c[0]), "+f"(c[1]), "+f"(c[2]), "+f"(c[3])
        : "r"(a[0]), "r"(a[1]), "r"(a[2]), "r"(a[3]), "r"(b0), "r"(b1));
}

// ---------------- init ----------------
__global__ void init_k() {
    int i = blockIdx.x * blockDim.x + threadIdx.x;
    if (i < N_NODES) g_deg[i] = 0;
    if (i < N_GRAPHS * HID) g_hg[i] = 0.0f;
    if (i < N_GRAPHS) g_gcnt[i] = 0.0f;
}

// ---------------- weight prep: split + fragment-order ----------------
// slot = ((kt*32 + nt)*32 + lane)*2 + reg
// element: k = kt*16 + (lane&3)*2 + reg*8 (+0/+1 packed), n = nt*8 + lane/4
__global__ void prep_k(const float* __restrict__ W_emb,
                       const float* __restrict__ Ws) {
    int i = blockIdx.x * blockDim.x + threadIdx.x;
    if (i >= WF_U32) return;
    const float* Wsrc;
    int r;
    if (i < EMB_U32) { r = i; Wsrc = W_emb; }
    else {
        int j = i - EMB_U32;
        int l = j / LYR_U32;
        r = j % LYR_U32;
        Wsrc = Ws + (size_t)l * 512 * 256;
    }
    int reg = r & 1;
    int lane = (r >> 1) & 31;
    int tile = r >> 6;
    int nt = tile & 31;
    int kt = tile >> 5;
    int k = kt * 16 + (lane & 3) * 2 + reg * 8;
    int n = nt * 8 + (lane >> 2);
    float w0 = Wsrc[(size_t)k * 256 + n];
    float w1 = Wsrc[(size_t)(k + 1) * 256 + n];
    uint32_t h, l;
    split2(make_float2(w0, w1), h, l);
    g_wfh[i] = h;
    g_wfl[i] = l;
}

// ---------------- CSR build ----------------
__global__ void deg_k(const int* __restrict__ dst) {
    int i = blockIdx.x * blockDim.x + threadIdx.x;
    if (i < N_EDGES) atomicAdd(&g_deg[dst[i]], 1);
}

__global__ void scan_k() {
    __shared__ int sh[1024];
    __shared__ int base_s;
    int tid = threadIdx.x;
    if (tid == 0) base_s = 0;
    __syncthreads();
    for (int start = 0; start < N_NODES; start += 1024) {
        int i = start + tid;
        int v = (i < N_NODES) ? g_deg[i] : 0;
        sh[tid] = v;
        __syncthreads();
        for (int off = 1; off < 1024; off <<= 1) {
            int t = (tid >= off) ? sh[tid - off] : 0;
            __syncthreads();
            sh[tid] += t;
            __syncthreads();
        }
        int incl = sh[tid];
        int total = sh[1023];
        int base = base_s;
        if (i < N_NODES) {
            int ro = base + incl - v;
            g_rowoff[i] = ro;
            g_cursor[i] = ro;
            g_inv[i] = 1.0f / (float)(v > 0 ? v : 1);
        }
        __syncthreads();
        if (tid == 0) base_s = base + total;
        __syncthreads();
    }
    if (tid == 0) g_rowoff[N_NODES] = base_s;
}

__global__ void fill_k(const int* __restrict__ src, const int* __restrict__ dst) {
    int i = blockIdx.x * blockDim.x + threadIdx.x;
    if (i < N_EDGES) {
        int d = dst[i];
        int p = atomicAdd(&g_cursor[d], 1);
        g_csr[p] = src[i];
    }
}

// ---------------- mean aggregation ----------------
__global__ void __launch_bounds__(256) agg_k(int sel) {
    const float* xs = sel ? g_x1 : g_x0;
    int gw = (blockIdx.x * blockDim.x + threadIdx.x) >> 5;
    int lane = threadIdx.x & 31;
    if (gw >= N_NODES) return;
    int beg = g_rowoff[gw];
    int end = g_rowoff[gw + 1];
    float4 s0 = make_float4(0.f, 0.f, 0.f, 0.f);
    float4 s1 = make_float4(0.f, 0.f, 0.f, 0.f);
    #pragma unroll 2
    for (int j = beg; j < end; j++) {
        int s = g_csr[j];
        const float4* xr = (const float4*)(xs + (size_t)s * HID);
        float4 a = xr[lane];
        float4 b = xr[lane + 32];
        s0.x += a.x; s0.y += a.y; s0.z += a.z; s0.w += a.w;
        s1.x += b.x; s1.y += b.y; s1.z += b.z; s1.w += b.w;
    }
    float inv = g_inv[gw];
    s0.x *= inv; s0.y *= inv; s0.z *= inv; s0.w *= inv;
    s1.x *= inv; s1.y *= inv; s1.z *= inv; s1.w *= inv;
    float4* cr = (float4*)(g_c + (size_t)gw * HID);
    cr[lane] = s0;
    cr[lane + 32] = s1;
}

// ---------------- 3xBF16 mma.sync fused GEMM ----------------
// CTA: 256 thr = 8 warps (2M x 4N); tile 64 rows x 256 cols.
// MODE 0: x0 = h @ W_emb + b          (K=128)
// MODE 1: bundle = [xin|c] @ W + b; xout = xin + relu(bundle/max(||.||,eps))
template <int MODE>
__global__ void __launch_bounds__(256) tgemm_k(const float* __restrict__ Aext,
                                               const float* __restrict__ bias,
                                               int fragoff, int sel) {
    const int K = MODE ? 512 : 128;
    const int NCH = K / 16;
    const int lda = MODE ? 256 : 128;

    int tid = threadIdx.x;
    int lane = tid & 31;
    int wid = tid >> 5;
    int wm = wid >> 2;      // 0..1
    int wn = wid & 3;       // 0..3
    int g = lane >> 2;
    int t = lane & 3;
    int row0 = blockIdx.x * 64;

    const float* xin = sel ? g_x1 : g_x0;
    float* xout = (MODE == 0) ? g_x0 : (sel ? g_x0 : g_x1);

    __shared__ float ssq[64];
    __shared__ float rinv[64];
    __shared__ float biasS[256];
    if (tid < 64) ssq[tid] = 0.0f;
    if (tid < 128) {
        float2 bv = ((const float2*)bias)[tid];
        biasS[2 * tid] = bv.x;
        biasS[2 * tid + 1] = bv.y;
    }

    float acc[2][8][4];
    #pragma unroll
    for (int m = 0; m < 2; m++)
        #pragma unroll
        for (int j = 0; j < 8; j++)
            #pragma unroll
            for (int q = 0; q < 4; q++) acc[m][j][q] = 0.0f;

    const uint2* WH = (const uint2*)(g_wfh + fragoff);
    const uint2* WL = (const uint2*)(g_wfl + fragoff);
    int bbase = (wn * 8) * 32 + lane;

    for (int ch = 0; ch < NCH; ch++) {
        // ---- A fragments: load fp32, split hi/lo ----
        const float* Asrc;
        int acol;
        if (MODE == 0) { Asrc = Aext; acol = ch * 16; }
        else if (ch < 16) { Asrc = xin; acol = ch * 16; }
        else { Asrc = g_c; acol = ch * 16 - 256; }

        uint32_t ah[2][4], al[2][4];
        #pragma unroll
        for (int mt = 0; mt < 2; mt++) {
            int r = row0 + wm * 32 + mt * 16 + g;
            const float* p = Asrc + (size_t)r * lda + acol + 2 * t;
            float2 f0, f1, f2, f3;
            bool z0 = (MODE == 0) && (r >= N_NODES);
            bool z1 = (MODE == 0) && (r + 8 >= N_NODES);
            f0 = z0 ? make_float2(0.f, 0.f) : *(const float2*)p;
            f2 = z0 ? make_float2(0.f, 0.f) : *(const float2*)(p + 8);
            f1 = z1 ? make_float2(0.f, 0.f) : *(const float2*)(p + (size_t)8 * lda);
            f3 = z1 ? make_float2(0.f, 0.f) : *(const float2*)(p + (size_t)8 * lda + 8);
            split2(f0, ah[mt][0], al[mt][0]);
            split2(f1, ah[mt][1], al[mt][1]);
            split2(f2, ah[mt][2], al[mt][2]);
            split2(f3, ah[mt][3], al[mt][3]);
        }

        // ---- B fragments: pre-split, fragment-ordered ----
        uint2 bh[8], bl[8];
        const uint2* ph = WH + (size_t)(ch * 32) * 32 + bbase;
        const uint2* pl = WL + (size_t)(ch * 32) * 32 + bbase;
        #pragma unroll
        for (int j = 0; j < 8; j++) {
            bh[j] = ph[j * 32];
            bl[j] = pl[j * 32];
        }

        // ---- 3-term MMAs ----
        #pragma unroll
        for (int mt = 0; mt < 2; mt++) {
            #pragma unroll
            for (int j = 0; j < 8; j++) {
                mma16816(acc[mt][j], ah[mt], bh[j].x, bh[j].y);
                mma16816(acc[mt][j], al[mt], bh[j].x, bh[j].y);
                mma16816(acc[mt][j], ah[mt], bl[j].x, bl[j].y);
            }
        }
    }

    __syncthreads();   // biasS ready; ssq zeroed

    if (MODE == 1) {
        // rowwise sum of squares (bias added first)
        #pragma unroll
        for (int mt = 0; mt < 2; mt++) {
            float p0 = 0.f, p1 = 0.f;
            #pragma unroll
            for (int j = 0; j < 8; j++) {
                int n0 = wn * 64 + j * 8 + 2 * t;
                float b0 = biasS[n0], b1 = biasS[n0 + 1];
                float v0 = acc[mt][j][0] + b0;
                float v1 = acc[mt][j][1] + b1;
                float v2 = acc[mt][j][2] + b0;
                float v3 = acc[mt][j][3] + b1;
                p0 += v0 * v0 + v1 * v1;
                p1 += v2 * v2 + v3 * v3;
            }
            p0 += __shfl_xor_sync(0xffffffffu, p0, 1);
            p0 += __shfl_xor_sync(0xffffffffu, p0, 2);
            p1 += __shfl_xor_sync(0xffffffffu, p1, 1);
            p1 += __shfl_xor_sync(0xffffffffu, p1, 2);
            if (t == 0) {
                atomicAdd(&ssq[wm * 32 + mt * 16 + g], p0);
                atomicAdd(&ssq[wm * 32 + mt * 16 + 8 + g], p1);
            }
        }
        __syncthreads();
        if (tid < 64) rinv[tid] = 1.0f / fmaxf(sqrtf(ssq[tid]), 1e-12f);
        __syncthreads();
    }

    // ---- write output ----
    #pragma unroll
    for (int mt = 0; mt < 2; mt++) {
        int rl = wm * 32 + mt * 16 + g;
        int r = row0 + rl;
        float i0 = (MODE == 1) ? rinv[rl] : 0.f;
        float i1 = (MODE == 1) ? rinv[rl + 8] : 0.f;
        #pragma unroll
        for (int j = 0; j < 8; j++) {
            int n0 = wn * 64 + j * 8 + 2 * t;
            float b0 = biasS[n0], b1 = biasS[n0 + 1];
            float v0 = acc[mt][j][0] + b0;
            float v1 = acc[mt][j][1] + b1;
            float v2 = acc[mt][j][2] + b0;
            float v3 = acc[mt][j][3] + b1;
            if (MODE == 0) {
                *(float2*)&xout[(size_t)r * 256 + n0] = make_float2(v0, v1);
                *(float2*)&xout[(size_t)(r + 8) * 256 + n0] = make_float2(v2, v3);
            } else {
                float2 o0 = *(const float2*)&xin[(size_t)r * 256 + n0];
                o0.x += fmaxf(v0, 0.f) * i0;
                o0.y += fmaxf(v1, 0.f) * i0;
                *(float2*)&xout[(size_t)r * 256 + n0] = o0;
                float2 o1 = *(const float2*)&xin[(size_t)(r + 8) * 256 + n0];
                o1.x += fmaxf(v2, 0.f) * i1;
                o1.y += fmaxf(v3, 0.f) * i1;
                *(float2*)&xout[(size_t)(r + 8) * 256 + n0] = o1;
            }
        }
    }
}

// ---------------- graph mean pool + readout ----------------
__global__ void accum_k(const int* __restrict__ gid) {
    int n = blockIdx.x;
    int c = threadIdx.x;
    int g = gid[n];
    atomicAdd(&g_hg[g * HID + c], g_x0[(size_t)n * HID + c]);
    if (c == 0) atomicAdd(&g_gcnt[g], 1.0f);
}

__global__ void final_k(const float* __restrict__ p_pos,
                        const float* __restrict__ p_neg,
                        const float* __restrict__ W_fc,
                        float* __restrict__ out) {
    __shared__ float ss[N_GRAPHS][10];
    int t = threadIdx.x;
    if (t < N_GRAPHS * 10) {
        int g = t / 10;
        int p = t % 10;
        const float* P = (p < 5) ? (p_pos + p * HID) : (p_neg + (p - 5) * HID);
        float invc = 1.0f / fmaxf(g_gcnt[g], 1.0f);
        float d = 0.0f;
        for (int c = 0; c < HID; c++) {
            float diff = g_hg[g * HID + c] * invc - P[c];
            d += diff * diff;
        }
        ss[g][p] = logf((d + 1.0f) / (d + 1e-12f));
    }
    __syncthreads();
    if (t < N_GRAPHS) {
        float y = 0.0f;
        #pragma unroll
        for (int j = 0; j < 10; j++) y += ss[t][j] * W_fc[j];
        out[t] = 1.0f / (1.0f + expf(-y));
    }
}

// ---------------- launch ----------------
extern "C" void kernel_launch(void* const* d_in, const int* in_sizes, int n_in,
                              void* d_out, int out_size) {
    const float* h      = (const float*)d_in[0];
    const int*   src    = (const int*)d_in[1];
    const int*   dst    = (const int*)d_in[2];
    const int*   gid    = (const int*)d_in[3];
    const float* W_emb  = (const float*)d_in[4];
    const float* b_emb  = (const float*)d_in[5];
    const float* Ws     = (const float*)d_in[6];
    const float* bs     = (const float*)d_in[7];
    const float* p_pos  = (const float*)d_in[8];
    const float* p_neg  = (const float*)d_in[9];
    const float* W_fc   = (const float*)d_in[10];
    float* out = (float*)d_out;

    prep_k<<<(WF_U32 + 255) / 256, 256>>>(W_emb, Ws);
    init_k<<<(N_NODES + 255) / 256, 256>>>();
    deg_k<<<(N_EDGES + 255) / 256, 256>>>(dst);
    scan_k<<<1, 1024>>>();
    fill_k<<<(N_EDGES + 255) / 256, 256>>>(src, dst);

    tgemm_k<0><<<MT64, 256>>>(h, b_emb, 0, 0);

    for (int l = 0; l < N_LAYERS; l++) {
        int sel = l & 1;
        agg_k<<<(N_NODES * 32 + 255) / 256, 256>>>(sel);
        tgemm_k<1><<<MT64, 256>>>(nullptr, bs + (size_t)l * HID,
                                  EMB_U32 + l * LYR_U32, sel);
    }

    accum_k<<<N_NODES, 256>>>(gid);
    final_k<<<1, 640>>>(p_pos, p_neg, W_fc, out);
}

// round 4
// speedup vs baseline: 1.8231x; 1.1616x over previous
#include <cuda_runtime.h>
#include <cuda_bf16.h>
#include <cstdint>

// ---------------- problem constants ----------------
#define N_NODES   50000
#define N_EDGES   800000
#define N_GRAPHS  64
#define IN_DIM    128
#define HID       256
#define N_LAYERS  4
#define NPAD      50048   // 64*782
#define MT64      782
#define NB        196     // scan blocks: 196*256 = 50176 >= N_NODES

// fragment-ordered weight arrays (u32 slots, each = bf16x2)
#define EMB_U32   (8*32*32*2)
#define LYR_U32   (32*32*32*2)
#define WF_U32    (EMB_U32 + 4*LYR_U32)

// ---------------- device scratch ----------------
__device__ float    g_x0[(size_t)NPAD * HID];
__device__ float    g_x1[(size_t)NPAD * HID];
__device__ float    g_c[(size_t)NPAD * HID];
__device__ uint4    g_xb[(size_t)NPAD * 32];   // bf16 copy of x, 32 uint4 per row
__device__ uint32_t g_wfh[WF_U32];
__device__ uint32_t g_wfl[WF_U32];
__device__ int      g_deg[N_NODES];
__device__ int      g_rowoff[N_NODES + 1];
__device__ int      g_cursor[N_NODES];
__device__ int      g_csr[N_EDGES];
__device__ float    g_inv[N_NODES];
__device__ int      g_bsum[NB];
__device__ int      g_boff[NB];
__device__ float    g_hg[N_GRAPHS * HID];
__device__ float    g_gcnt[N_GRAPHS];

// ---------------- helpers ----------------
__device__ __forceinline__ uint32_t pk2(float lo, float hi) {
    uint32_t p;
    asm("cvt.rn.bf16x2.f32 %0, %1, %2;" : "=r"(p) : "f"(hi), "f"(lo));
    return p;
}
__device__ __forceinline__ void split2(float2 v, uint32_t& h, uint32_t& l) {
    uint32_t hp = pk2(v.x, v.y);
    float h0 = __uint_as_float(hp << 16);
    float h1 = __uint_as_float(hp & 0xffff0000u);
    h = hp;
    l = pk2(v.x - h0, v.y - h1);
}
__device__ __forceinline__ float blo(uint32_t u) { return __uint_as_float(u << 16); }
__device__ __forceinline__ float bhi(uint32_t u) { return __uint_as_float(u & 0xffff0000u); }

__device__ __forceinline__ void mma16816(float* c, const uint32_t* a,
                                         uint32_t b0, uint32_t b1) {
    asm volatile(
        "mma.sync.aligned.m16n8k16.row.col.f32.bf16.bf16.f32 "
        "{%0,%1,%2,%3}, {%4,%5,%6,%7}, {%8,%9}, {%0,%1,%2,%3};"
        : "+f"(c[0]), "+f"(c[1]), "+f"(c[2]), "+f"(c[3])
        : "r"(a[0]), "r"(a[1]), "r"(a[2]), "r"(a[3]), "r"(b0), "r"(b1));
}

// ---------------- init ----------------
__global__ void init_k() {
    int i = blockIdx.x * blockDim.x + threadIdx.x;
    if (i < N_NODES) g_deg[i] = 0;
    if (i < N_GRAPHS * HID) g_hg[i] = 0.0f;
    if (i < N_GRAPHS) g_gcnt[i] = 0.0f;
}

// ---------------- weight prep ----------------
__global__ void prep_k(const float* __restrict__ W_emb,
                       const float* __restrict__ Ws) {
    int i = blockIdx.x * blockDim.x + threadIdx.x;
    if (i >= WF_U32) return;
    const float* Wsrc;
    int r;
    if (i < EMB_U32) { r = i; Wsrc = W_emb; }
    else {
        int j = i - EMB_U32;
        int l = j / LYR_U32;
        r = j % LYR_U32;
        Wsrc = Ws + (size_t)l * 512 * 256;
    }
    int reg = r & 1;
    int lane = (r >> 1) & 31;
    int tile = r >> 6;
    int nt = tile & 31;
    int kt = tile >> 5;
    int k = kt * 16 + (lane & 3) * 2 + reg * 8;
    int n = nt * 8 + (lane >> 2);
    float w0 = Wsrc[(size_t)k * 256 + n];
    float w1 = Wsrc[(size_t)(k + 1) * 256 + n];
    uint32_t h, l;
    split2(make_float2(w0, w1), h, l);
    g_wfh[i] = h;
    g_wfl[i] = l;
}

// ---------------- CSR build ----------------
__global__ void deg_k(const int* __restrict__ dst) {
    int i = blockIdx.x * blockDim.x + threadIdx.x;
    if (i < N_EDGES) atomicAdd(&g_deg[dst[i]], 1);
}

__device__ __forceinline__ int block_scan_incl(int v, int* wt) {
    int t = threadIdx.x;
    int s = v;
    #pragma unroll
    for (int off = 1; off < 32; off <<= 1) {
        int u = __shfl_up_sync(0xffffffffu, s, off);
        if ((t & 31) >= off) s += u;
    }
    if ((t & 31) == 31) wt[t >> 5] = s;
    __syncthreads();
    if (t < 8) {
        int w = wt[t];
        #pragma unroll
        for (int off = 1; off < 8; off <<= 1) {
            int u = __shfl_up_sync(0xffu, w, off);
            if (t >= off) w += u;
        }
        wt[t] = w;
    }
    __syncthreads();
    return s + ((t >= 32) ? wt[(t >> 5) - 1] : 0);
}

__global__ void scanA_k() {
    __shared__ int wt[8];
    int i = blockIdx.x * 256 + threadIdx.x;
    int v = (i < N_NODES) ? g_deg[i] : 0;
    int incl = block_scan_incl(v, wt);
    if (i < N_NODES) g_rowoff[i] = incl - v;
    if (threadIdx.x == 255) g_bsum[blockIdx.x] = incl;
}

__global__ void scanB_k() {
    __shared__ int wt[8];
    int t = threadIdx.x;
    int v = (t < NB) ? g_bsum[t] : 0;
    int incl = block_scan_incl(v, wt);
    if (t < NB) g_boff[t] = incl - v;
    if (t == NB - 1) g_rowoff[N_NODES] = incl;
}

__global__ void scanC_k() {
    int i = blockIdx.x * 256 + threadIdx.x;
    if (i >= N_NODES) return;
    int ro = g_rowoff[i] + g_boff[blockIdx.x];
    g_rowoff[i] = ro;
    g_cursor[i] = ro;
    int d = g_deg[i];
    g_inv[i] = 1.0f / (float)(d > 0 ? d : 1);
}

__global__ void fill_k(const int* __restrict__ src, const int* __restrict__ dst) {
    int i = blockIdx.x * blockDim.x + threadIdx.x;
    if (i < N_EDGES) {
        int d = dst[i];
        int p = atomicAdd(&g_cursor[d], 1);
        g_csr[p] = src[i];
    }
}

// ---------------- mean aggregation (bf16 source) ----------------
__global__ void __launch_bounds__(256) agg_k() {
    int gw = (blockIdx.x * blockDim.x + threadIdx.x) >> 5;
    int lane = threadIdx.x & 31;
    if (gw >= N_NODES) return;
    int beg = g_rowoff[gw];
    int end = g_rowoff[gw + 1];
    float s[8] = {0.f, 0.f, 0.f, 0.f, 0.f, 0.f, 0.f, 0.f};
    #pragma unroll 2
    for (int j = beg; j < end; j++) {
        int sn = g_csr[j];
        uint4 v = g_xb[(size_t)sn * 32 + lane];
        s[0] += blo(v.x); s[1] += bhi(v.x);
        s[2] += blo(v.y); s[3] += bhi(v.y);
        s[4] += blo(v.z); s[5] += bhi(v.z);
        s[6] += blo(v.w); s[7] += bhi(v.w);
    }
    float inv = g_inv[gw];
    #pragma unroll
    for (int q = 0; q < 8; q++) s[q] *= inv;
    float* cr = g_c + (size_t)gw * HID + lane * 8;
    *(float4*)cr = make_float4(s[0], s[1], s[2], s[3]);
    *(float4*)(cr + 4) = make_float4(s[4], s[5], s[6], s[7]);
}

// ---------------- 2-term bf16 mma.sync fused GEMM ----------------
// a = bf16(rn) of A ; b = hi+lo split (precomputed) -> A_fp32-ish x B_fp32-ish
// CTA: 256 thr = 8 warps (2M x 4N); tile 64 rows x 256 cols.
template <int MODE>
__global__ void __launch_bounds__(256) tgemm_k(const float* __restrict__ Aext,
                                               const float* __restrict__ bias,
                                               int fragoff, int sel) {
    const int K = MODE ? 512 : 128;
    const int NCH = K / 16;
    const int lda = MODE ? 256 : 128;

    int tid = threadIdx.x;
    int lane = tid & 31;
    int wid = tid >> 5;
    int wm = wid >> 2;
    int wn = wid & 3;
    int g = lane >> 2;
    int t = lane & 3;
    int row0 = blockIdx.x * 64;

    const float* xin = sel ? g_x1 : g_x0;
    float* xout = (MODE == 0) ? g_x0 : (sel ? g_x0 : g_x1);
    uint32_t* xb32 = (uint32_t*)g_xb;

    __shared__ float ssq[64];
    __shared__ float rinv[64];
    __shared__ float biasS[256];
    if (tid < 64) ssq[tid] = 0.0f;
    if (tid < 128) {
        float2 bv = ((const float2*)bias)[tid];
        biasS[2 * tid] = bv.x;
        biasS[2 * tid + 1] = bv.y;
    }

    float acc[2][8][4];
    #pragma unroll
    for (int m = 0; m < 2; m++)
        #pragma unroll
        for (int j = 0; j < 8; j++)
            #pragma unroll
            for (int q = 0; q < 4; q++) acc[m][j][q] = 0.0f;

    const uint2* WH = (const uint2*)(g_wfh + fragoff);
    const uint2* WL = (const uint2*)(g_wfl + fragoff);
    int bbase = (wn * 8) * 32 + lane;

    for (int ch = 0; ch < NCH; ch++) {
        const float* Asrc;
        int acol;
        if (MODE == 0) { Asrc = Aext; acol = ch * 16; }
        else if (ch < 16) { Asrc = xin; acol = ch * 16; }
        else { Asrc = g_c; acol = ch * 16 - 256; }

        uint32_t ah[2][4];
        #pragma unroll
        for (int mt = 0; mt < 2; mt++) {
            int r = row0 + wm * 32 + mt * 16 + g;
            const float* p = Asrc + (size_t)r * lda + acol + 2 * t;
            float2 f0, f1, f2, f3;
            bool z0 = (MODE == 0) && (r >= N_NODES);
            bool z1 = (MODE == 0) && (r + 8 >= N_NODES);
            f0 = z0 ? make_float2(0.f, 0.f) : *(const float2*)p;
            f2 = z0 ? make_float2(0.f, 0.f) : *(const float2*)(p + 8);
            f1 = z1 ? make_float2(0.f, 0.f) : *(const float2*)(p + (size_t)8 * lda);
            f3 = z1 ? make_float2(0.f, 0.f) : *(const float2*)(p + (size_t)8 * lda + 8);
            ah[mt][0] = pk2(f0.x, f0.y);
            ah[mt][1] = pk2(f1.x, f1.y);
            ah[mt][2] = pk2(f2.x, f2.y);
            ah[mt][3] = pk2(f3.x, f3.y);
        }

        uint2 bh[8], bl[8];
        const uint2* ph = WH + (size_t)(ch * 32) * 32 + bbase;
        const uint2* pl = WL + (size_t)(ch * 32) * 32 + bbase;
        #pragma unroll
        for (int j = 0; j < 8; j++) {
            bh[j] = ph[j * 32];
            bl[j] = pl[j * 32];
        }

        #pragma unroll
        for (int mt = 0; mt < 2; mt++) {
            #pragma unroll
            for (int j = 0; j < 8; j++) {
                mma16816(acc[mt][j], ah[mt], bh[j].x, bh[j].y);
                mma16816(acc[mt][j], ah[mt], bl[j].x, bl[j].y);
            }
        }
    }

    __syncthreads();

    if (MODE == 1) {
        #pragma unroll
        for (int mt = 0; mt < 2; mt++) {
            float p0 = 0.f, p1 = 0.f;
            #pragma unroll
            for (int j = 0; j < 8; j++) {
                int n0 = wn * 64 + j * 8 + 2 * t;
                float b0 = biasS[n0], b1 = biasS[n0 + 1];
                float v0 = acc[mt][j][0] + b0;
                float v1 = acc[mt][j][1] + b1;
                float v2 = acc[mt][j][2] + b0;
                float v3 = acc[mt][j][3] + b1;
                p0 += v0 * v0 + v1 * v1;
                p1 += v2 * v2 + v3 * v3;
            }
            p0 += __shfl_xor_sync(0xffffffffu, p0, 1);
            p0 += __shfl_xor_sync(0xffffffffu, p0, 2);
            p1 += __shfl_xor_sync(0xffffffffu, p1, 1);
            p1 += __shfl_xor_sync(0xffffffffu, p1, 2);
            if (t == 0) {
                atomicAdd(&ssq[wm * 32 + mt * 16 + g], p0);
                atomicAdd(&ssq[wm * 32 + mt * 16 + 8 + g], p1);
            }
        }
        __syncthreads();
        if (tid < 64) rinv[tid] = 1.0f / fmaxf(sqrtf(ssq[tid]), 1e-12f);
        __syncthreads();
    }

    #pragma unroll
    for (int mt = 0; mt < 2; mt++) {
        int rl = wm * 32 + mt * 16 + g;
        int r = row0 + rl;
        float i0 = (MODE == 1) ? rinv[rl] : 0.f;
        float i1 = (MODE == 1) ? rinv[rl + 8] : 0.f;
        #pragma unroll
        for (int j = 0; j < 8; j++) {
            int n0 = wn * 64 + j * 8 + 2 * t;
            float b0 = biasS[n0], b1 = biasS[n0 + 1];
            float v0 = acc[mt][j][0] + b0;
            float v1 = acc[mt][j][1] + b1;
            float v2 = acc[mt][j][2] + b0;
            float v3 = acc[mt][j][3] + b1;
            if (MODE == 0) {
                *(float2*)&xout[(size_t)r * 256 + n0] = make_float2(v0, v1);
                *(float2*)&xout[(size_t)(r + 8) * 256 + n0] = make_float2(v2, v3);
                xb32[(size_t)r * 128 + n0 / 2] = pk2(v0, v1);
                xb32[(size_t)(r + 8) * 128 + n0 / 2] = pk2(v2, v3);
            } else {
                float2 o0 = *(const float2*)&xin[(size_t)r * 256 + n0];
                o0.x += fmaxf(v0, 0.f) * i0;
                o0.y += fmaxf(v1, 0.f) * i0;
                *(float2*)&xout[(size_t)r * 256 + n0] = o0;
                xb32[(size_t)r * 128 + n0 / 2] = pk2(o0.x, o0.y);
                float2 o1 = *(const float2*)&xin[(size_t)(r + 8) * 256 + n0];
                o1.x += fmaxf(v2, 0.f) * i1;
                o1.y += fmaxf(v3, 0.f) * i1;
                *(float2*)&xout[(size_t)(r + 8) * 256 + n0] = o1;
                xb32[(size_t)(r + 8) * 128 + n0 / 2] = pk2(o1.x, o1.y);
            }
        }
    }
}

// ---------------- graph mean pool (sorted graph_id, run-length fused) ------
__global__ void accum_k(const int* __restrict__ gid) {
    int b = blockIdx.x;
    int c = threadIdx.x;
    int n0 = b * 256;
    int n1 = min(n0 + 256, N_NODES);
    float sum = 0.0f, cnt = 0.0f;
    int cur = gid[n0];
    for (int n = n0; n < n1; n++) {
        int gg = gid[n];
        if (gg != cur) {
            atomicAdd(&g_hg[cur * HID + c], sum);
            if (c == 0) atomicAdd(&g_gcnt[cur], cnt);
            sum = 0.0f; cnt = 0.0f; cur = gg;
        }
        sum += g_x0[(size_t)n * HID + c];
        cnt += 1.0f;
    }
    atomicAdd(&g_hg[cur * HID + c], sum);
    if (c == 0) atomicAdd(&g_gcnt[cur], cnt);
}

__global__ void final_k(const float* __restrict__ p_pos,
                        const float* __restrict__ p_neg,
                        const float* __restrict__ W_fc,
                        float* __restrict__ out) {
    __shared__ float ss[N_GRAPHS][10];
    int t = threadIdx.x;
    if (t < N_GRAPHS * 10) {
        int g = t / 10;
        int p = t % 10;
        const float* P = (p < 5) ? (p_pos + p * HID) : (p_neg + (p - 5) * HID);
        float invc = 1.0f / fmaxf(g_gcnt[g], 1.0f);
        float d = 0.0f;
        for (int c = 0; c < HID; c++) {
            float diff = g_hg[g * HID + c] * invc - P[c];
            d += diff * diff;
        }
        ss[g][p] = logf((d + 1.0f) / (d + 1e-12f));
    }
    __syncthreads();
    if (t < N_GRAPHS) {
        float y = 0.0f;
        #pragma unroll
        for (int j = 0; j < 10; j++) y += ss[t][j] * W_fc[j];
        out[t] = 1.0f / (1.0f + expf(-y));
    }
}

// ---------------- launch ----------------
extern "C" void kernel_launch(void* const* d_in, const int* in_sizes, int n_in,
                              void* d_out, int out_size) {
    const float* h      = (const float*)d_in[0];
    const int*   src    = (const int*)d_in[1];
    const int*   dst    = (const int*)d_in[2];
    const int*   gid    = (const int*)d_in[3];
    const float* W_emb  = (const float*)d_in[4];
    const float* b_emb  = (const float*)d_in[5];
    const float* Ws     = (const float*)d_in[6];
    const float* bs     = (const float*)d_in[7];
    const float* p_pos  = (const float*)d_in[8];
    const float* p_neg  = (const float*)d_in[9];
    const float* W_fc   = (const float*)d_in[10];
    float* out = (float*)d_out;

    prep_k<<<(WF_U32 + 255) / 256, 256>>>(W_emb, Ws);
    init_k<<<(N_NODES + 255) / 256, 256>>>();
    deg_k<<<(N_EDGES + 255) / 256, 256>>>(dst);
    scanA_k<<<NB, 256>>>();
    scanB_k<<<1, 256>>>();
    scanC_k<<<NB, 256>>>();
    fill_k<<<(N_EDGES + 255) / 256, 256>>>(src, dst);

    tgemm_k<0><<<MT64, 256>>>(h, b_emb, 0, 0);

    for (int l = 0; l < N_LAYERS; l++) {
        int sel = l & 1;
        agg_k<<<(N_NODES * 32 + 255) / 256, 256>>>();
        tgemm_k<1><<<MT64, 256>>>(nullptr, bs + (size_t)l * HID,
                                  EMB_U32 + l * LYR_U32, sel);
    }

    accum_k<<<NB, 256>>>(gid);
    final_k<<<1, 640>>>(p_pos, p_neg, W_fc, out);
}

// round 5
// speedup vs baseline: 2.0104x; 1.1027x over previous
#include <cuda_runtime.h>
#include <cuda_bf16.h>
#include <cstdint>

// ---------------- problem constants ----------------
#define N_NODES   50000
#define N_EDGES   800000
#define N_GRAPHS  64
#define IN_DIM    128
#define HID       256
#define N_LAYERS  4
#define NPAD      50048   // 64*782
#define MT64      782
#define NB        196     // scan blocks: 196*256 = 50176 >= N_NODES

// fragment-ordered weight array (u32 slots, each = bf16x2)
#define EMB_U32   (8*32*32*2)
#define LYR_U32   (32*32*32*2)
#define WF_U32    (EMB_U32 + 4*LYR_U32)

// ---------------- device scratch ----------------
__device__ float    g_x0[(size_t)NPAD * HID];
__device__ float    g_x1[(size_t)NPAD * HID];
__device__ uint32_t g_xb[(size_t)NPAD * 128];  // bf16 copy of x (128 u32 per row)
__device__ uint32_t g_cb[(size_t)NPAD * 128];  // bf16 aggregated c
__device__ uint32_t g_wfh[WF_U32];
__device__ int      g_deg[N_NODES];
__device__ int      g_rowoff[N_NODES + 1];
__device__ int      g_cursor[N_NODES];
__device__ int      g_csr[N_EDGES];
__device__ float    g_inv[N_NODES];
__device__ int      g_bsum[NB];
__device__ int      g_boff[NB];
__device__ float    g_hg[N_GRAPHS * HID];
__device__ float    g_gcnt[N_GRAPHS];

// ---------------- helpers ----------------
__device__ __forceinline__ uint32_t pk2(float lo, float hi) {
    uint32_t p;
    asm("cvt.rn.bf16x2.f32 %0, %1, %2;" : "=r"(p) : "f"(hi), "f"(lo));
    return p;
}
__device__ __forceinline__ float blo(uint32_t u) { return __uint_as_float(u << 16); }
__device__ __forceinline__ float bhi(uint32_t u) { return __uint_as_float(u & 0xffff0000u); }

__device__ __forceinline__ void mma16816(float* c, const uint32_t* a,
                                         uint32_t b0, uint32_t b1) {
    asm volatile(
        "mma.sync.aligned.m16n8k16.row.col.f32.bf16.bf16.f32 "
        "{%0,%1,%2,%3}, {%4,%5,%6,%7}, {%8,%9}, {%0,%1,%2,%3};"
        : "+f"(c[0]), "+f"(c[1]), "+f"(c[2]), "+f"(c[3])
        : "r"(a[0]), "r"(a[1]), "r"(a[2]), "r"(a[3]), "r"(b0), "r"(b1));
}

// ---------------- init ----------------
__global__ void init_k() {
    int i = blockIdx.x * blockDim.x + threadIdx.x;
    if (i < N_NODES) g_deg[i] = 0;
    if (i < N_GRAPHS * HID) g_hg[i] = 0.0f;
    if (i < N_GRAPHS) g_gcnt[i] = 0.0f;
}

// ---------------- weight prep (bf16 rn, fragment-ordered) ----------------
__global__ void prep_k(const float* __restrict__ W_emb,
                       const float* __restrict__ Ws) {
    int i = blockIdx.x * blockDim.x + threadIdx.x;
    if (i >= WF_U32) return;
    const float* Wsrc;
    int r;
    if (i < EMB_U32) { r = i; Wsrc = W_emb; }
    else {
        int j = i - EMB_U32;
        int l = j / LYR_U32;
        r = j % LYR_U32;
        Wsrc = Ws + (size_t)l * 512 * 256;
    }
    int reg = r & 1;
    int lane = (r >> 1) & 31;
    int tile = r >> 6;
    int nt = tile & 31;
    int kt = tile >> 5;
    int k = kt * 16 + (lane & 3) * 2 + reg * 8;
    int n = nt * 8 + (lane >> 2);
    float w0 = Wsrc[(size_t)k * 256 + n];
    float w1 = Wsrc[(size_t)(k + 1) * 256 + n];
    g_wfh[i] = pk2(w0, w1);
}

// ---------------- CSR build ----------------
__global__ void deg_k(const int* __restrict__ dst) {
    int i = blockIdx.x * blockDim.x + threadIdx.x;
    if (i < N_EDGES) atomicAdd(&g_deg[dst[i]], 1);
}

__device__ __forceinline__ int block_scan_incl(int v, int* wt) {
    int t = threadIdx.x;
    int s = v;
    #pragma unroll
    for (int off = 1; off < 32; off <<= 1) {
        int u = __shfl_up_sync(0xffffffffu, s, off);
        if ((t & 31) >= off) s += u;
    }
    if ((t & 31) == 31) wt[t >> 5] = s;
    __syncthreads();
    if (t < 8) {
        int w = wt[t];
        #pragma unroll
        for (int off = 1; off < 8; off <<= 1) {
            int u = __shfl_up_sync(0xffu, w, off);
            if (t >= off) w += u;
        }
        wt[t] = w;
    }
    __syncthreads();
    return s + ((t >= 32) ? wt[(t >> 5) - 1] : 0);
}

__global__ void scanA_k() {
    __shared__ int wt[8];
    int i = blockIdx.x * 256 + threadIdx.x;
    int v = (i < N_NODES) ? g_deg[i] : 0;
    int incl = block_scan_incl(v, wt);
    if (i < N_NODES) g_rowoff[i] = incl - v;
    if (threadIdx.x == 255) g_bsum[blockIdx.x] = incl;
}

__global__ void scanB_k() {
    __shared__ int wt[8];
    int t = threadIdx.x;
    int v = (t < NB) ? g_bsum[t] : 0;
    int incl = block_scan_incl(v, wt);
    if (t < NB) g_boff[t] = incl - v;
    if (t == NB - 1) g_rowoff[N_NODES] = incl;
}

__global__ void scanC_k() {
    int i = blockIdx.x * 256 + threadIdx.x;
    if (i >= N_NODES) return;
    int ro = g_rowoff[i] + g_boff[blockIdx.x];
    g_rowoff[i] = ro;
    g_cursor[i] = ro;
    int d = g_deg[i];
    g_inv[i] = 1.0f / (float)(d > 0 ? d : 1);
}

__global__ void fill_k(const int* __restrict__ src, const int* __restrict__ dst) {
    int i = blockIdx.x * blockDim.x + threadIdx.x;
    if (i < N_EDGES) {
        int d = dst[i];
        int p = atomicAdd(&g_cursor[d], 1);
        g_csr[p] = src[i];
    }
}

// ---------------- mean aggregation (bf16 in, bf16 out) ----------------
__global__ void __launch_bounds__(256) agg_k() {
    int gw = (blockIdx.x * blockDim.x + threadIdx.x) >> 5;
    int lane = threadIdx.x & 31;
    if (gw >= N_NODES) return;
    int beg = g_rowoff[gw];
    int end = g_rowoff[gw + 1];
    float s[8] = {0.f, 0.f, 0.f, 0.f, 0.f, 0.f, 0.f, 0.f};
    const uint4* xb4 = (const uint4*)g_xb;
    #pragma unroll 2
    for (int j = beg; j < end; j++) {
        int sn = g_csr[j];
        uint4 v = xb4[(size_t)sn * 32 + lane];
        s[0] += blo(v.x); s[1] += bhi(v.x);
        s[2] += blo(v.y); s[3] += bhi(v.y);
        s[4] += blo(v.z); s[5] += bhi(v.z);
        s[6] += blo(v.w); s[7] += bhi(v.w);
    }
    float inv = g_inv[gw];
    uint4 o;
    o.x = pk2(s[0] * inv, s[1] * inv);
    o.y = pk2(s[2] * inv, s[3] * inv);
    o.z = pk2(s[4] * inv, s[5] * inv);
    o.w = pk2(s[6] * inv, s[7] * inv);
    ((uint4*)g_cb)[(size_t)gw * 32 + lane] = o;
}

// ---------------- 1-term bf16 mma.sync fused GEMM ----------------
// CTA: 256 thr = 8 warps (2M x 4N); tile 64 rows x 256 cols.
// MODE 0: x0/xb = h @ W_emb + b (K=128, A from fp32 ext)
// MODE 1: bundle = [xb|cb] @ W + b; xout = xin + relu(bundle/max(||.||,eps))
template <int MODE>
__global__ void __launch_bounds__(256) tgemm_k(const float* __restrict__ Aext,
                                               const float* __restrict__ bias,
                                               int fragoff, int sel) {
    const int K = MODE ? 512 : 128;
    const int NCH = K / 16;

    int tid = threadIdx.x;
    int lane = tid & 31;
    int wid = tid >> 5;
    int wm = wid >> 2;
    int wn = wid & 3;
    int g = lane >> 2;
    int t = lane & 3;
    int row0 = blockIdx.x * 64;

    const float* xin = sel ? g_x1 : g_x0;
    float* xout = (MODE == 0) ? g_x0 : (sel ? g_x0 : g_x1);

    __shared__ float ssq[64];
    __shared__ float rinv[64];
    __shared__ float biasS[256];
    if (tid < 64) ssq[tid] = 0.0f;
    if (tid < 128) {
        float2 bv = ((const float2*)bias)[tid];
        biasS[2 * tid] = bv.x;
        biasS[2 * tid + 1] = bv.y;
    }

    float acc[2][8][4];
    #pragma unroll
    for (int m = 0; m < 2; m++)
        #pragma unroll
        for (int j = 0; j < 8; j++)
            #pragma unroll
            for (int q = 0; q < 4; q++) acc[m][j][q] = 0.0f;

    const uint2* WH = (const uint2*)(g_wfh + fragoff);
    int bbase = (wn * 8) * 32 + lane;

    for (int ch = 0; ch < NCH; ch++) {
        uint32_t ah[2][4];
        if (MODE == 0) {
            int acol = ch * 16;
            #pragma unroll
            for (int mt = 0; mt < 2; mt++) {
                int r = row0 + wm * 32 + mt * 16 + g;
                const float* p = Aext + (size_t)r * 128 + acol + 2 * t;
                float2 f0, f1, f2, f3;
                bool z0 = (r >= N_NODES);
                bool z1 = (r + 8 >= N_NODES);
                f0 = z0 ? make_float2(0.f, 0.f) : *(const float2*)p;
                f2 = z0 ? make_float2(0.f, 0.f) : *(const float2*)(p + 8);
                f1 = z1 ? make_float2(0.f, 0.f) : *(const float2*)(p + (size_t)8 * 128);
                f3 = z1 ? make_float2(0.f, 0.f) : *(const float2*)(p + (size_t)8 * 128 + 8);
                ah[mt][0] = pk2(f0.x, f0.y);
                ah[mt][1] = pk2(f1.x, f1.y);
                ah[mt][2] = pk2(f2.x, f2.y);
                ah[mt][3] = pk2(f3.x, f3.y);
            }
        } else {
            const uint32_t* Ab = (ch < 16) ? g_xb : g_cb;
            int kb2 = (ch < 16) ? ch * 8 : ch * 8 - 128;   // u32 index in row
            #pragma unroll
            for (int mt = 0; mt < 2; mt++) {
                int r = row0 + wm * 32 + mt * 16 + g;
                const uint32_t* p = Ab + (size_t)r * 128 + kb2 + t;
                ah[mt][0] = p[0];
                ah[mt][1] = p[(size_t)8 * 128];
                ah[mt][2] = p[4];
                ah[mt][3] = p[(size_t)8 * 128 + 4];
            }
        }

        uint2 bh[8];
        const uint2* ph = WH + (size_t)(ch * 32) * 32 + bbase;
        #pragma unroll
        for (int j = 0; j < 8; j++) bh[j] = ph[j * 32];

        #pragma unroll
        for (int mt = 0; mt < 2; mt++)
            #pragma unroll
            for (int j = 0; j < 8; j++)
                mma16816(acc[mt][j], ah[mt], bh[j].x, bh[j].y);
    }

    __syncthreads();

    if (MODE == 1) {
        #pragma unroll
        for (int mt = 0; mt < 2; mt++) {
            float p0 = 0.f, p1 = 0.f;
            #pragma unroll
            for (int j = 0; j < 8; j++) {
                int n0 = wn * 64 + j * 8 + 2 * t;
                float b0 = biasS[n0], b1 = biasS[n0 + 1];
                float v0 = acc[mt][j][0] + b0;
                float v1 = acc[mt][j][1] + b1;
                float v2 = acc[mt][j][2] + b0;
                float v3 = acc[mt][j][3] + b1;
                p0 += v0 * v0 + v1 * v1;
                p1 += v2 * v2 + v3 * v3;
            }
            p0 += __shfl_xor_sync(0xffffffffu, p0, 1);
            p0 += __shfl_xor_sync(0xffffffffu, p0, 2);
            p1 += __shfl_xor_sync(0xffffffffu, p1, 1);
            p1 += __shfl_xor_sync(0xffffffffu, p1, 2);
            if (t == 0) {
                atomicAdd(&ssq[wm * 32 + mt * 16 + g], p0);
                atomicAdd(&ssq[wm * 32 + mt * 16 + 8 + g], p1);
            }
        }
        __syncthreads();
        if (tid < 64) rinv[tid] = 1.0f / fmaxf(sqrtf(ssq[tid]), 1e-12f);
        __syncthreads();
    }

    #pragma unroll
    for (int mt = 0; mt < 2; mt++) {
        int rl = wm * 32 + mt * 16 + g;
        int r = row0 + rl;
        float i0 = (MODE == 1) ? rinv[rl] : 0.f;
        float i1 = (MODE == 1) ? rinv[rl + 8] : 0.f;
        #pragma unroll
        for (int j = 0; j < 8; j++) {
            int n0 = wn * 64 + j * 8 + 2 * t;
            float b0 = biasS[n0], b1 = biasS[n0 + 1];
            float v0 = acc[mt][j][0] + b0;
            float v1 = acc[mt][j][1] + b1;
            float v2 = acc[mt][j][2] + b0;
            float v3 = acc[mt][j][3] + b1;
            if (MODE == 0) {
                *(float2*)&xout[(size_t)r * 256 + n0] = make_float2(v0, v1);
                *(float2*)&xout[(size_t)(r + 8) * 256 + n0] = make_float2(v2, v3);
                g_xb[(size_t)r * 128 + n0 / 2] = pk2(v0, v1);
                g_xb[(size_t)(r + 8) * 128 + n0 / 2] = pk2(v2, v3);
            } else {
                float2 o0 = *(const float2*)&xin[(size_t)r * 256 + n0];
                o0.x += fmaxf(v0, 0.f) * i0;
                o0.y += fmaxf(v1, 0.f) * i0;
                *(float2*)&xout[(size_t)r * 256 + n0] = o0;
                g_xb[(size_t)r * 128 + n0 / 2] = pk2(o0.x, o0.y);
                float2 o1 = *(const float2*)&xin[(size_t)(r + 8) * 256 + n0];
                o1.x += fmaxf(v2, 0.f) * i1;
                o1.y += fmaxf(v3, 0.f) * i1;
                *(float2*)&xout[(size_t)(r + 8) * 256 + n0] = o1;
                g_xb[(size_t)(r + 8) * 128 + n0 / 2] = pk2(o1.x, o1.y);
            }
        }
    }
}

// ---------------- graph mean pool (sorted graph_id, run-length fused) ------
__global__ void accum_k(const int* __restrict__ gid) {
    int b = blockIdx.x;
    int c = threadIdx.x;
    int n0 = b * 256;
    int n1 = min(n0 + 256, N_NODES);
    float sum = 0.0f, cnt = 0.0f;
    int cur = gid[n0];
    for (int n = n0; n < n1; n++) {
        int gg = gid[n];
        if (gg != cur) {
            atomicAdd(&g_hg[cur * HID + c], sum);
            if (c == 0) atomicAdd(&g_gcnt[cur], cnt);
            sum = 0.0f; cnt = 0.0f; cur = gg;
        }
        sum += g_x0[(size_t)n * HID + c];
        cnt += 1.0f;
    }
    atomicAdd(&g_hg[cur * HID + c], sum);
    if (c == 0) atomicAdd(&g_gcnt[cur], cnt);
}

__global__ void final_k(const float* __restrict__ p_pos,
                        const float* __restrict__ p_neg,
                        const float* __restrict__ W_fc,
                        float* __restrict__ out) {
    __shared__ float ss[N_GRAPHS][10];
    int t = threadIdx.x;
    if (t < N_GRAPHS * 10) {
        int g = t / 10;
        int p = t % 10;
        const float* P = (p < 5) ? (p_pos + p * HID) : (p_neg + (p - 5) * HID);
        float invc = 1.0f / fmaxf(g_gcnt[g], 1.0f);
        float d = 0.0f;
        for (int c = 0; c < HID; c++) {
            float diff = g_hg[g * HID + c] * invc - P[c];
            d += diff * diff;
        }
        ss[g][p] = logf((d + 1.0f) / (d + 1e-12f));
    }
    __syncthreads();
    if (t < N_GRAPHS) {
        float y = 0.0f;
        #pragma unroll
        for (int j = 0; j < 10; j++) y += ss[t][j] * W_fc[j];
        out[t] = 1.0f / (1.0f + expf(-y));
    }
}

// ---------------- launch ----------------
extern "C" void kernel_launch(void* const* d_in, const int* in_sizes, int n_in,
                              void* d_out, int out_size) {
    const float* h      = (const float*)d_in[0];
    const int*   src    = (const int*)d_in[1];
    const int*   dst    = (const int*)d_in[2];
    const int*   gid    = (const int*)d_in[3];
    const float* W_emb  = (const float*)d_in[4];
    const float* b_emb  = (const float*)d_in[5];
    const float* Ws     = (const float*)d_in[6];
    const float* bs     = (const float*)d_in[7];
    const float* p_pos  = (const float*)d_in[8];
    const float* p_neg  = (const float*)d_in[9];
    const float* W_fc   = (const float*)d_in[10];
    float* out = (float*)d_out;

    prep_k<<<(WF_U32 + 255) / 256, 256>>>(W_emb, Ws);
    init_k<<<(N_NODES + 255) / 256, 256>>>();
    deg_k<<<(N_EDGES + 255) / 256, 256>>>(dst);
    scanA_k<<<NB, 256>>>();
    scanB_k<<<1, 256>>>();
    scanC_k<<<NB, 256>>>();
    fill_k<<<(N_EDGES + 255) / 256, 256>>>(src, dst);

    tgemm_k<0><<<MT64, 256>>>(h, b_emb, 0, 0);

    for (int l = 0; l < N_LAYERS; l++) {
        int sel = l & 1;
        agg_k<<<(N_NODES * 32 + 255) / 256, 256>>>();
        tgemm_k<1><<<MT64, 256>>>(nullptr, bs + (size_t)l * HID,
                                  EMB_U32 + l * LYR_U32, sel);
    }

    accum_k<<<NB, 256>>>(gid);
    final_k<<<1, 640>>>(p_pos, p_neg, W_fc, out);
}

// round 6
// speedup vs baseline: 2.2025x; 1.0956x over previous
#include <cuda_runtime.h>
#include <cuda_bf16.h>
#include <cstdint>

// ---------------- problem constants ----------------
#define N_NODES   50000
#define N_EDGES   800000
#define N_GRAPHS  64
#define IN_DIM    128
#define HID       256
#define N_LAYERS  4
#define NPAD      50048   // 64*782
#define MT64      782
#define NB        196

// fp8 fragment-ordered weights (u32 slots, each = 4 x e4m3)
#define EMB_F8    (4*32*32*2)     // ktiles(32-chunks)=4
#define LYR_F8    (16*32*32*2)    // ktiles=16
#define WF8_U32   (EMB_F8 + 4*LYR_F8)

#define XSCL 8.0f     // x stored in fp8 as 8*x
#define WSCL 16.0f    // W stored in fp8 as 16*W
#define INV_XW (1.0f/(XSCL*WSCL))
#define INV_W  (1.0f/WSCL)

// ---------------- device scratch ----------------
__device__ uint32_t g_xb[(size_t)NPAD * 128];   // bf16 canonical x
__device__ uint32_t g_xf8[(size_t)NPAD * 64];   // e4m3 8*x
__device__ uint32_t g_cf8[(size_t)NPAD * 64];   // e4m3 8*c
__device__ uint32_t g_wf8[WF8_U32];
__device__ int      g_deg[N_NODES];
__device__ int      g_rowoff[N_NODES + 1];
__device__ int      g_cursor[N_NODES];
__device__ int      g_csr[N_EDGES];
__device__ float    g_inv[N_NODES];
__device__ int      g_bsum[NB];
__device__ int      g_boff[NB];
__device__ float    g_hg[N_GRAPHS * HID];
__device__ float    g_gcnt[N_GRAPHS];

// ---------------- helpers ----------------
__device__ __forceinline__ uint32_t pk2(float lo, float hi) {
    uint32_t p;
    asm("cvt.rn.bf16x2.f32 %0, %1, %2;" : "=r"(p) : "f"(hi), "f"(lo));
    return p;
}
__device__ __forceinline__ float blo(uint32_t u) { return __uint_as_float(u << 16); }
__device__ __forceinline__ float bhi(uint32_t u) { return __uint_as_float(u & 0xffff0000u); }

__device__ __forceinline__ unsigned short pk_e2(float f0, float f1) {
    unsigned short d;
    asm("cvt.rn.satfinite.e4m3x2.f32 %0, %1, %2;" : "=h"(d) : "f"(f1), "f"(f0));
    return d;
}
__device__ __forceinline__ uint32_t pk_e4(float f0, float f1, float f2, float f3) {
    unsigned short lo = pk_e2(f0, f1), hi = pk_e2(f2, f3);
    uint32_t r;
    asm("mov.b32 %0, {%1, %2};" : "=r"(r) : "h"(lo), "h"(hi));
    return r;
}
// accumulate 4 e4m3 bytes (one u32) into two f16x2 accumulators
__device__ __forceinline__ void acc_f8(uint32_t v, uint32_t& sA, uint32_t& sB) {
    unsigned short lo, hi;
    asm("mov.b32 {%0, %1}, %2;" : "=h"(lo), "=h"(hi) : "r"(v));
    uint32_t fA, fB;
    asm("cvt.rn.f16x2.e4m3x2 %0, %1;" : "=r"(fA) : "h"(lo));
    asm("cvt.rn.f16x2.e4m3x2 %0, %1;" : "=r"(fB) : "h"(hi));
    asm("add.rn.f16x2 %0, %0, %1;" : "+r"(sA) : "r"(fA));
    asm("add.rn.f16x2 %0, %0, %1;" : "+r"(sB) : "r"(fB));
}
__device__ __forceinline__ float2 up_h2(uint32_t v) {
    unsigned short lo, hi;
    asm("mov.b32 {%0, %1}, %2;" : "=h"(lo), "=h"(hi) : "r"(v));
    float a, b;
    asm("cvt.f32.f16 %0, %1;" : "=f"(a) : "h"(lo));
    asm("cvt.f32.f16 %0, %1;" : "=f"(b) : "h"(hi));
    return make_float2(a, b);
}

__device__ __forceinline__ void mma_f8(float* c, const uint32_t* a,
                                       uint32_t b0, uint32_t b1) {
    asm volatile(
        "mma.sync.aligned.m16n8k32.row.col.f32.e4m3.e4m3.f32 "
        "{%0,%1,%2,%3}, {%4,%5,%6,%7}, {%8,%9}, {%0,%1,%2,%3};"
        : "+f"(c[0]), "+f"(c[1]), "+f"(c[2]), "+f"(c[3])
        : "r"(a[0]), "r"(a[1]), "r"(a[2]), "r"(a[3]), "r"(b0), "r"(b1));
}

// ---------------- init ----------------
__global__ void init_k() {
    int i = blockIdx.x * blockDim.x + threadIdx.x;
    if (i < N_NODES) g_deg[i] = 0;
    if (i < N_GRAPHS * HID) g_hg[i] = 0.0f;
    if (i < N_GRAPHS) g_gcnt[i] = 0.0f;
}

// ---------------- weight prep: x16 scale, e4m3, fragment-ordered ----------
// slot i -> reg(2/lane), lane(32), tile = kt*32+nt
// k0 = kt*32 + (lane&3)*4 + reg*16 ; bytes b=0..3 -> k0+b ; n = nt*8 + lane/4
__global__ void prep_k(const float* __restrict__ W_emb,
                       const float* __restrict__ Ws) {
    int i = blockIdx.x * blockDim.x + threadIdx.x;
    if (i >= WF8_U32) return;
    const float* Wsrc;
    int r;
    if (i < EMB_F8) { r = i; Wsrc = W_emb; }
    else {
        int j = i - EMB_F8;
        int l = j / LYR_F8;
        r = j % LYR_F8;
        Wsrc = Ws + (size_t)l * 512 * 256;
    }
    int reg = r & 1;
    int lane = (r >> 1) & 31;
    int tile = r >> 6;
    int nt = tile & 31;
    int kt = tile >> 5;
    int k0 = kt * 32 + (lane & 3) * 4 + reg * 16;
    int n = nt * 8 + (lane >> 2);
    float w0 = Wsrc[(size_t)k0 * 256 + n] * WSCL;
    float w1 = Wsrc[(size_t)(k0 + 1) * 256 + n] * WSCL;
    float w2 = Wsrc[(size_t)(k0 + 2) * 256 + n] * WSCL;
    float w3 = Wsrc[(size_t)(k0 + 3) * 256 + n] * WSCL;
    g_wf8[i] = pk_e4(w0, w1, w2, w3);
}

// ---------------- CSR build ----------------
__global__ void deg_k(const int* __restrict__ dst) {
    int i = blockIdx.x * blockDim.x + threadIdx.x;
    if (i < N_EDGES) atomicAdd(&g_deg[dst[i]], 1);
}

__device__ __forceinline__ int block_scan_incl(int v, int* wt) {
    int t = threadIdx.x;
    int s = v;
    #pragma unroll
    for (int off = 1; off < 32; off <<= 1) {
        int u = __shfl_up_sync(0xffffffffu, s, off);
        if ((t & 31) >= off) s += u;
    }
    if ((t & 31) == 31) wt[t >> 5] = s;
    __syncthreads();
    if (t < 8) {
        int w = wt[t];
        #pragma unroll
        for (int off = 1; off < 8; off <<= 1) {
            int u = __shfl_up_sync(0xffu, w, off);
            if (t >= off) w += u;
        }
        wt[t] = w;
    }
    __syncthreads();
    return s + ((t >= 32) ? wt[(t >> 5) - 1] : 0);
}

__global__ void scanA_k() {
    __shared__ int wt[8];
    int i = blockIdx.x * 256 + threadIdx.x;
    int v = (i < N_NODES) ? g_deg[i] : 0;
    int incl = block_scan_incl(v, wt);
    if (i < N_NODES) g_rowoff[i] = incl - v;
    if (threadIdx.x == 255) g_bsum[blockIdx.x] = incl;
}

__global__ void scanB_k() {
    __shared__ int wt[8];
    int t = threadIdx.x;
    int v = (t < NB) ? g_bsum[t] : 0;
    int incl = block_scan_incl(v, wt);
    if (t < NB) g_boff[t] = incl - v;
    if (t == NB - 1) g_rowoff[N_NODES] = incl;
}

__global__ void scanC_k() {
    int i = blockIdx.x * 256 + threadIdx.x;
    if (i >= N_NODES) return;
    int ro = g_rowoff[i] + g_boff[blockIdx.x];
    g_rowoff[i] = ro;
    g_cursor[i] = ro;
    int d = g_deg[i];
    g_inv[i] = 1.0f / (float)(d > 0 ? d : 1);
}

__global__ void fill_k(const int* __restrict__ src, const int* __restrict__ dst) {
    int i = blockIdx.x * blockDim.x + threadIdx.x;
    if (i < N_EDGES) {
        int d = dst[i];
        int p = atomicAdd(&g_cursor[d], 1);
        g_csr[p] = src[i];
    }
}

// ---------------- mean aggregation: fp8 in, f16x2 accum, fp8 out ----------
__global__ void __launch_bounds__(256) agg_k() {
    int gw = (blockIdx.x * blockDim.x + threadIdx.x) >> 5;
    int lane = threadIdx.x & 31;
    if (gw >= N_NODES) return;
    int beg = g_rowoff[gw];
    int end = g_rowoff[gw + 1];
    uint32_t s0 = 0, s1 = 0, s2 = 0, s3 = 0;   // f16x2 accumulators
    const uint2* xf = (const uint2*)g_xf8;
    #pragma unroll 2
    for (int j = beg; j < end; j++) {
        int sn = g_csr[j];
        uint2 v = xf[(size_t)sn * 32 + lane];
        acc_f8(v.x, s0, s1);
        acc_f8(v.y, s2, s3);
    }
    float inv = g_inv[gw];
    float2 a = up_h2(s0), b = up_h2(s1), c = up_h2(s2), d = up_h2(s3);
    uint2 o;
    o.x = pk_e4(a.x * inv, a.y * inv, b.x * inv, b.y * inv);
    o.y = pk_e4(c.x * inv, c.y * inv, d.x * inv, d.y * inv);
    ((uint2*)g_cf8)[(size_t)gw * 32 + lane] = o;
}

// ---------------- fp8 mma.sync fused GEMM (in-place x update) -------------
// CTA: 256 thr = 8 warps (2M x 4N); tile 64 rows x 256 cols; K-chunk = 32.
// MODE 0: x = h @ (16 W_emb)/16 + b ; write xb(bf16) + xf8(e4m3 8x)
// MODE 1: bundle = [8x|8c] @ (16W)/128 + b ; x += relu(bundle/max(||.||,eps))
template <int MODE>
__global__ void __launch_bounds__(256) tgemm_k(const float* __restrict__ Aext,
                                               const float* __restrict__ bias,
                                               int fragoff) {
    const int NCH = MODE ? 16 : 4;

    int tid = threadIdx.x;
    int lane = tid & 31;
    int wid = tid >> 5;
    int wm = wid >> 2;
    int wn = wid & 3;
    int g = lane >> 2;
    int t = lane & 3;
    int row0 = blockIdx.x * 64;

    __shared__ float ssq[64];
    __shared__ float rinv[64];
    __shared__ float biasS[256];
    if (tid < 64) ssq[tid] = 0.0f;
    if (tid < 128) {
        float2 bv = ((const float2*)bias)[tid];
        biasS[2 * tid] = bv.x;
        biasS[2 * tid + 1] = bv.y;
    }

    float acc[2][8][4];
    #pragma unroll
    for (int m = 0; m < 2; m++)
        #pragma unroll
        for (int j = 0; j < 8; j++)
            #pragma unroll
            for (int q = 0; q < 4; q++) acc[m][j][q] = 0.0f;

    const uint2* WF = (const uint2*)(g_wf8 + fragoff);
    int bbase = (wn * 8) * 32 + lane;

    for (int ch = 0; ch < NCH; ch++) {
        uint32_t ah[2][4];
        if (MODE == 0) {
            int acol = ch * 32;
            #pragma unroll
            for (int mt = 0; mt < 2; mt++) {
                int r = row0 + wm * 32 + mt * 16 + g;
                const float* p = Aext + (size_t)r * 128 + acol + 4 * t;
                bool z0 = (r >= N_NODES);
                bool z1 = (r + 8 >= N_NODES);
                float4 f0 = z0 ? make_float4(0.f, 0.f, 0.f, 0.f) : *(const float4*)p;
                float4 f2 = z0 ? make_float4(0.f, 0.f, 0.f, 0.f) : *(const float4*)(p + 16);
                float4 f1 = z1 ? make_float4(0.f, 0.f, 0.f, 0.f)
                               : *(const float4*)(p + (size_t)8 * 128);
                float4 f3 = z1 ? make_float4(0.f, 0.f, 0.f, 0.f)
                               : *(const float4*)(p + (size_t)8 * 128 + 16);
                ah[mt][0] = pk_e4(f0.x, f0.y, f0.z, f0.w);
                ah[mt][1] = pk_e4(f1.x, f1.y, f1.z, f1.w);
                ah[mt][2] = pk_e4(f2.x, f2.y, f2.z, f2.w);
                ah[mt][3] = pk_e4(f3.x, f3.y, f3.z, f3.w);
            }
        } else {
            const uint32_t* Ab = (ch < 8) ? g_xf8 : g_cf8;
            int base = (ch < 8) ? ch * 8 : (ch - 8) * 8;   // u32 idx in 64-u32 row
            #pragma unroll
            for (int mt = 0; mt < 2; mt++) {
                int r = row0 + wm * 32 + mt * 16 + g;
                const uint32_t* p = Ab + (size_t)r * 64 + base + t;
                ah[mt][0] = p[0];
                ah[mt][1] = p[(size_t)8 * 64];
                ah[mt][2] = p[4];
                ah[mt][3] = p[(size_t)8 * 64 + 4];
            }
        }

        uint2 bh[8];
        const uint2* ph = WF + (size_t)(ch * 32) * 32 + bbase;
        #pragma unroll
        for (int j = 0; j < 8; j++) bh[j] = ph[j * 32];

        #pragma unroll
        for (int mt = 0; mt < 2; mt++)
            #pragma unroll
            for (int j = 0; j < 8; j++)
                mma_f8(acc[mt][j], ah[mt], bh[j].x, bh[j].y);
    }

    __syncthreads();   // all mainloop xf8/cf8 reads done; biasS/ssq visible

    const float cs = MODE ? INV_XW : INV_W;

    if (MODE == 1) {
        #pragma unroll
        for (int mt = 0; mt < 2; mt++) {
            float p0 = 0.f, p1 = 0.f;
            #pragma unroll
            for (int j = 0; j < 8; j++) {
                int n0 = wn * 64 + j * 8 + 2 * t;
                float b0 = biasS[n0], b1 = biasS[n0 + 1];
                float v0 = acc[mt][j][0] * cs + b0;
                float v1 = acc[mt][j][1] * cs + b1;
                float v2 = acc[mt][j][2] * cs + b0;
                float v3 = acc[mt][j][3] * cs + b1;
                p0 += v0 * v0 + v1 * v1;
                p1 += v2 * v2 + v3 * v3;
            }
            p0 += __shfl_xor_sync(0xffffffffu, p0, 1);
            p0 += __shfl_xor_sync(0xffffffffu, p0, 2);
            p1 += __shfl_xor_sync(0xffffffffu, p1, 1);
            p1 += __shfl_xor_sync(0xffffffffu, p1, 2);
            if (t == 0) {
                atomicAdd(&ssq[wm * 32 + mt * 16 + g], p0);
                atomicAdd(&ssq[wm * 32 + mt * 16 + 8 + g], p1);
            }
        }
        __syncthreads();
        if (tid < 64) rinv[tid] = 1.0f / fmaxf(sqrtf(ssq[tid]), 1e-12f);
        __syncthreads();
    }

    unsigned short* xf16 = (unsigned short*)g_xf8;

    #pragma unroll
    for (int mt = 0; mt < 2; mt++) {
        int rl = wm * 32 + mt * 16 + g;
        int r = row0 + rl;
        float i0 = (MODE == 1) ? rinv[rl] : 0.f;
        float i1 = (MODE == 1) ? rinv[rl + 8] : 0.f;
        #pragma unroll
        for (int j = 0; j < 8; j++) {
            int n0 = wn * 64 + j * 8 + 2 * t;
            float b0 = biasS[n0], b1 = biasS[n0 + 1];
            float v0 = acc[mt][j][0] * cs + b0;
            float v1 = acc[mt][j][1] * cs + b1;
            float v2 = acc[mt][j][2] * cs + b0;
            float v3 = acc[mt][j][3] * cs + b1;
            size_t u0 = (size_t)r * 128 + n0 / 2;
            size_t u1 = (size_t)(r + 8) * 128 + n0 / 2;
            if (MODE == 0) {
                g_xb[u0] = pk2(v0, v1);
                g_xb[u1] = pk2(v2, v3);
                xf16[u0] = pk_e2(v0 * XSCL, v1 * XSCL);
                xf16[u1] = pk_e2(v2 * XSCL, v3 * XSCL);
            } else {
                uint32_t xw0 = g_xb[u0];
                float o0 = blo(xw0) + fmaxf(v0, 0.f) * i0;
                float o1 = bhi(xw0) + fmaxf(v1, 0.f) * i0;
                g_xb[u0] = pk2(o0, o1);
                xf16[u0] = pk_e2(o0 * XSCL, o1 * XSCL);
                uint32_t xw1 = g_xb[u1];
                float o2 = blo(xw1) + fmaxf(v2, 0.f) * i1;
                float o3 = bhi(xw1) + fmaxf(v3, 0.f) * i1;
                g_xb[u1] = pk2(o2, o3);
                xf16[u1] = pk_e2(o2 * XSCL, o3 * XSCL);
            }
        }
    }
}

// ---------------- graph mean pool (sorted graph_id, run-length fused) ------
__global__ void accum_k(const int* __restrict__ gid) {
    int b = blockIdx.x;
    int c = threadIdx.x;
    int n0 = b * 256;
    int n1 = min(n0 + 256, N_NODES);
    float sum = 0.0f, cnt = 0.0f;
    int cur = gid[n0];
    for (int n = n0; n < n1; n++) {
        int gg = gid[n];
        if (gg != cur) {
            atomicAdd(&g_hg[cur * HID + c], sum);
            if (c == 0) atomicAdd(&g_gcnt[cur], cnt);
            sum = 0.0f; cnt = 0.0f; cur = gg;
        }
        uint32_t w = g_xb[(size_t)n * 128 + (c >> 1)];
        sum += (c & 1) ? bhi(w) : blo(w);
        cnt += 1.0f;
    }
    atomicAdd(&g_hg[cur * HID + c], sum);
    if (c == 0) atomicAdd(&g_gcnt[cur], cnt);
}

__global__ void final_k(const float* __restrict__ p_pos,
                        const float* __restrict__ p_neg,
                        const float* __restrict__ W_fc,
                        float* __restrict__ out) {
    __shared__ float ss[N_GRAPHS][10];
    int t = threadIdx.x;
    if (t < N_GRAPHS * 10) {
        int g = t / 10;
        int p = t % 10;
        const float* P = (p < 5) ? (p_pos + p * HID) : (p_neg + (p - 5) * HID);
        float invc = 1.0f / fmaxf(g_gcnt[g], 1.0f);
        float d = 0.0f;
        for (int c = 0; c < HID; c++) {
            float diff = g_hg[g * HID + c] * invc - P[c];
            d += diff * diff;
        }
        ss[g][p] = logf((d + 1.0f) / (d + 1e-12f));
    }
    __syncthreads();
    if (t < N_GRAPHS) {
        float y = 0.0f;
        #pragma unroll
        for (int j = 0; j < 10; j++) y += ss[t][j] * W_fc[j];
        out[t] = 1.0f / (1.0f + expf(-y));
    }
}

// ---------------- launch ----------------
extern "C" void kernel_launch(void* const* d_in, const int* in_sizes, int n_in,
                              void* d_out, int out_size) {
    const float* h      = (const float*)d_in[0];
    const int*   src    = (const int*)d_in[1];
    const int*   dst    = (const int*)d_in[2];
    const int*   gid    = (const int*)d_in[3];
    const float* W_emb  = (const float*)d_in[4];
    const float* b_emb  = (const float*)d_in[5];
    const float* Ws     = (const float*)d_in[6];
    const float* bs     = (const float*)d_in[7];
    const float* p_pos  = (const float*)d_in[8];
    const float* p_neg  = (const float*)d_in[9];
    const float* W_fc   = (const float*)d_in[10];
    float* out = (float*)d_out;

    prep_k<<<(WF8_U32 + 255) / 256, 256>>>(W_emb, Ws);
    init_k<<<(N_NODES + 255) / 256, 256>>>();
    deg_k<<<(N_EDGES + 255) / 256, 256>>>(dst);
    scanA_k<<<NB, 256>>>();
    scanB_k<<<1, 256>>>();
    scanC_k<<<NB, 256>>>();
    fill_k<<<(N_EDGES + 255) / 256, 256>>>(src, dst);

    tgemm_k<0><<<MT64, 256>>>(h, b_emb, 0);

    for (int l = 0; l < N_LAYERS; l++) {
        agg_k<<<(N_NODES * 32 + 255) / 256, 256>>>();
        tgemm_k<1><<<MT64, 256>>>(nullptr, bs + (size_t)l * HID,
                                  EMB_F8 + l * LYR_F8);
    }

    accum_k<<<NB, 256>>>(gid);
    final_k<<<1, 640>>>(p_pos, p_neg, W_fc, out);
}

// round 7
// speedup vs baseline: 2.8410x; 1.2899x over previous
#include <cuda_runtime.h>
#include <cuda_bf16.h>
#include <cstdint>

// ---------------- problem constants ----------------
#define N_NODES   50000
#define N_EDGES   800000
#define N_GRAPHS  64
#define IN_DIM    128
#define HID       256
#define N_LAYERS  4
#define NPAD      50048   // 64*782
#define MT64      782
#define NB        196

// fp8 fragment-ordered weights (u32 slots, each = 4 x e4m3)
#define EMB_F8    (4*32*32*2)     // ktiles(32-chunks)=4
#define LYR_F8    (16*32*32*2)    // ktiles=16
#define WF8_U32   (EMB_F8 + 4*LYR_F8)

#define XSCL 8.0f     // x stored in fp8 as 8*x
#define WSCL 16.0f    // W stored in fp8 as 16*W
#define INV_XW (1.0f/(XSCL*WSCL))
#define INV_W  (1.0f/WSCL)

// ---------------- device scratch ----------------
__device__ uint32_t g_xb[(size_t)NPAD * 128];   // bf16 canonical x
__device__ uint32_t g_xf8[(size_t)NPAD * 64];   // e4m3 8*x
__device__ uint32_t g_cf8[(size_t)NPAD * 64];   // e4m3 8*c
__device__ uint32_t g_wf8[WF8_U32];
__device__ int      g_deg[N_NODES];
__device__ int      g_rowoff[N_NODES + 1];
__device__ int      g_cursor[N_NODES];
__device__ int      g_csr[N_EDGES];
__device__ float    g_inv[N_NODES];
__device__ int      g_bsum[NB];
__device__ int      g_boff[NB];
__device__ float    g_hg[N_GRAPHS * HID];
__device__ float    g_gcnt[N_GRAPHS];

// ---------------- helpers ----------------
__device__ __forceinline__ uint32_t pk2(float lo, float hi) {
    uint32_t p;
    asm("cvt.rn.bf16x2.f32 %0, %1, %2;" : "=r"(p) : "f"(hi), "f"(lo));
    return p;
}
__device__ __forceinline__ float blo(uint32_t u) { return __uint_as_float(u << 16); }
__device__ __forceinline__ float bhi(uint32_t u) { return __uint_as_float(u & 0xffff0000u); }

__device__ __forceinline__ unsigned short pk_e2(float f0, float f1) {
    unsigned short d;
    asm("cvt.rn.satfinite.e4m3x2.f32 %0, %1, %2;" : "=h"(d) : "f"(f1), "f"(f0));
    return d;
}
__device__ __forceinline__ uint32_t pk_e4(float f0, float f1, float f2, float f3) {
    unsigned short lo = pk_e2(f0, f1), hi = pk_e2(f2, f3);
    uint32_t r;
    asm("mov.b32 %0, {%1, %2};" : "=r"(r) : "h"(lo), "h"(hi));
    return r;
}
// accumulate 4 e4m3 bytes (one u32) into two f16x2 accumulators
__device__ __forceinline__ void acc_f8(uint32_t v, uint32_t& sA, uint32_t& sB) {
    unsigned short lo, hi;
    asm("mov.b32 {%0, %1}, %2;" : "=h"(lo), "=h"(hi) : "r"(v));
    uint32_t fA, fB;
    asm("cvt.rn.f16x2.e4m3x2 %0, %1;" : "=r"(fA) : "h"(lo));
    asm("cvt.rn.f16x2.e4m3x2 %0, %1;" : "=r"(fB) : "h"(hi));
    asm("add.rn.f16x2 %0, %0, %1;" : "+r"(sA) : "r"(fA));
    asm("add.rn.f16x2 %0, %0, %1;" : "+r"(sB) : "r"(fB));
}
__device__ __forceinline__ void hadd2(uint32_t& a, uint32_t b) {
    asm("add.rn.f16x2 %0, %0, %1;" : "+r"(a) : "r"(b));
}
__device__ __forceinline__ float2 up_h2(uint32_t v) {
    unsigned short lo, hi;
    asm("mov.b32 {%0, %1}, %2;" : "=h"(lo), "=h"(hi) : "r"(v));
    float a, b;
    asm("cvt.f32.f16 %0, %1;" : "=f"(a) : "h"(lo));
    asm("cvt.f32.f16 %0, %1;" : "=f"(b) : "h"(hi));
    return make_float2(a, b);
}

__device__ __forceinline__ void mma_f8(float* c, const uint32_t* a,
                                       uint32_t b0, uint32_t b1) {
    asm volatile(
        "mma.sync.aligned.m16n8k32.row.col.f32.e4m3.e4m3.f32 "
        "{%0,%1,%2,%3}, {%4,%5,%6,%7}, {%8,%9}, {%0,%1,%2,%3};"
        : "+f"(c[0]), "+f"(c[1]), "+f"(c[2]), "+f"(c[3])
        : "r"(a[0]), "r"(a[1]), "r"(a[2]), "r"(a[3]), "r"(b0), "r"(b1));
}

// ---------------- init ----------------
__global__ void init_k() {
    int i = blockIdx.x * blockDim.x + threadIdx.x;
    if (i < N_NODES) g_deg[i] = 0;
    if (i < N_GRAPHS * HID) g_hg[i] = 0.0f;
    if (i < N_GRAPHS) g_gcnt[i] = 0.0f;
}

// ---------------- weight prep: x16 scale, e4m3, fragment-ordered ----------
__global__ void prep_k(const float* __restrict__ W_emb,
                       const float* __restrict__ Ws) {
    int i = blockIdx.x * blockDim.x + threadIdx.x;
    if (i >= WF8_U32) return;
    const float* Wsrc;
    int r;
    if (i < EMB_F8) { r = i; Wsrc = W_emb; }
    else {
        int j = i - EMB_F8;
        int l = j / LYR_F8;
        r = j % LYR_F8;
        Wsrc = Ws + (size_t)l * 512 * 256;
    }
    int reg = r & 1;
    int lane = (r >> 1) & 31;
    int tile = r >> 6;
    int nt = tile & 31;
    int kt = tile >> 5;
    int k0 = kt * 32 + (lane & 3) * 4 + reg * 16;
    int n = nt * 8 + (lane >> 2);
    float w0 = Wsrc[(size_t)k0 * 256 + n] * WSCL;
    float w1 = Wsrc[(size_t)(k0 + 1) * 256 + n] * WSCL;
    float w2 = Wsrc[(size_t)(k0 + 2) * 256 + n] * WSCL;
    float w3 = Wsrc[(size_t)(k0 + 3) * 256 + n] * WSCL;
    g_wf8[i] = pk_e4(w0, w1, w2, w3);
}

// ---------------- CSR build ----------------
__global__ void deg_k(const int* __restrict__ dst) {
    int i = blockIdx.x * blockDim.x + threadIdx.x;
    if (i < N_EDGES) atomicAdd(&g_deg[dst[i]], 1);
}

__device__ __forceinline__ int block_scan_incl(int v, int* wt) {
    int t = threadIdx.x;
    int s = v;
    #pragma unroll
    for (int off = 1; off < 32; off <<= 1) {
        int u = __shfl_up_sync(0xffffffffu, s, off);
        if ((t & 31) >= off) s += u;
    }
    if ((t & 31) == 31) wt[t >> 5] = s;
    __syncthreads();
    if (t < 8) {
        int w = wt[t];
        #pragma unroll
        for (int off = 1; off < 8; off <<= 1) {
            int u = __shfl_up_sync(0xffu, w, off);
            if (t >= off) w += u;
        }
        wt[t] = w;
    }
    __syncthreads();
    return s + ((t >= 32) ? wt[(t >> 5) - 1] : 0);
}

__global__ void scanA_k() {
    __shared__ int wt[8];
    int i = blockIdx.x * 256 + threadIdx.x;
    int v = (i < N_NODES) ? g_deg[i] : 0;
    int incl = block_scan_incl(v, wt);
    if (i < N_NODES) g_rowoff[i] = incl - v;
    if (threadIdx.x == 255) g_bsum[blockIdx.x] = incl;
}

__global__ void scanB_k() {
    __shared__ int wt[8];
    int t = threadIdx.x;
    int v = (t < NB) ? g_bsum[t] : 0;
    int incl = block_scan_incl(v, wt);
    if (t < NB) g_boff[t] = incl - v;
    if (t == NB - 1) g_rowoff[N_NODES] = incl;
}

__global__ void scanC_k() {
    int i = blockIdx.x * 256 + threadIdx.x;
    if (i >= N_NODES) return;
    int ro = g_rowoff[i] + g_boff[blockIdx.x];
    g_rowoff[i] = ro;
    g_cursor[i] = ro;
    int d = g_deg[i];
    g_inv[i] = 1.0f / (float)(d > 0 ? d : 1);
}

__global__ void fill_k(const int* __restrict__ src, const int* __restrict__ dst) {
    int i = blockIdx.x * blockDim.x + threadIdx.x;
    if (i < N_EDGES) {
        int d = dst[i];
        int p = atomicAdd(&g_cursor[d], 1);
        g_csr[p] = src[i];
    }
}

// ---------------- mean aggregation: half-warp rows, 2 edges in flight ------
// One warp per node. Lanes 0-15 process edges beg,beg+2,... ; lanes 16-31
// process beg+1,beg+3,... Each half-warp covers the full 256B row as
// 16 lanes x uint4. Halves combined at the end via shfl_xor(16) + HADD2.
__global__ void __launch_bounds__(256) agg_k() {
    int gw = (blockIdx.x * blockDim.x + threadIdx.x) >> 5;
    int lane = threadIdx.x & 31;
    if (gw >= N_NODES) return;
    int half = lane >> 4;
    int hl = lane & 15;
    int beg = g_rowoff[gw];
    int end = g_rowoff[gw + 1];
    uint32_t s[8] = {0, 0, 0, 0, 0, 0, 0, 0};
    const uint4* xf = (const uint4*)g_xf8;
    #pragma unroll 2
    for (int j = beg + half; j < end; j += 2) {
        int sn = g_csr[j];
        uint4 v = xf[(size_t)sn * 16 + hl];
        acc_f8(v.x, s[0], s[1]);
        acc_f8(v.y, s[2], s[3]);
        acc_f8(v.z, s[4], s[5]);
        acc_f8(v.w, s[6], s[7]);
    }
    // combine the two half-warp partial sums (same columns at lane ^ 16)
    #pragma unroll
    for (int q = 0; q < 8; q++) {
        uint32_t o = __shfl_xor_sync(0xffffffffu, s[q], 16);
        hadd2(s[q], o);
    }
    if (half == 0) {
        float inv = g_inv[gw];
        float2 a0 = up_h2(s[0]), a1 = up_h2(s[1]);
        float2 a2 = up_h2(s[2]), a3 = up_h2(s[3]);
        float2 a4 = up_h2(s[4]), a5 = up_h2(s[5]);
        float2 a6 = up_h2(s[6]), a7 = up_h2(s[7]);
        uint4 o;
        o.x = pk_e4(a0.x * inv, a0.y * inv, a1.x * inv, a1.y * inv);
        o.y = pk_e4(a2.x * inv, a2.y * inv, a3.x * inv, a3.y * inv);
        o.z = pk_e4(a4.x * inv, a4.y * inv, a5.x * inv, a5.y * inv);
        o.w = pk_e4(a6.x * inv, a6.y * inv, a7.x * inv, a7.y * inv);
        ((uint4*)g_cf8)[(size_t)gw * 16 + hl] = o;
    }
}

// ---------------- fp8 mma.sync fused GEMM (in-place x update) -------------
// CTA: 256 thr = 8 warps (2M x 4N); tile 64 rows x 256 cols; K-chunk = 32.
template <int MODE>
__global__ void __launch_bounds__(256, 2) tgemm_k(const float* __restrict__ Aext,
                                                  const float* __restrict__ bias,
                                                  int fragoff) {
    const int NCH = MODE ? 16 : 4;

    int tid = threadIdx.x;
    int lane = tid & 31;
    int wid = tid >> 5;
    int wm = wid >> 2;
    int wn = wid & 3;
    int g = lane >> 2;
    int t = lane & 3;
    int row0 = blockIdx.x * 64;

    __shared__ float ssq[64];
    __shared__ float rinv[64];
    __shared__ float biasS[256];
    if (tid < 64) ssq[tid] = 0.0f;
    if (tid < 128) {
        float2 bv = ((const float2*)bias)[tid];
        biasS[2 * tid] = bv.x;
        biasS[2 * tid + 1] = bv.y;
    }

    float acc[2][8][4];
    #pragma unroll
    for (int m = 0; m < 2; m++)
        #pragma unroll
        for (int j = 0; j < 8; j++)
            #pragma unroll
            for (int q = 0; q < 4; q++) acc[m][j][q] = 0.0f;

    const uint2* WF = (const uint2*)(g_wf8 + fragoff);
    int bbase = (wn * 8) * 32 + lane;

    #pragma unroll
    for (int ch = 0; ch < NCH; ch++) {
        uint32_t ah[2][4];
        if (MODE == 0) {
            int acol = ch * 32;
            #pragma unroll
            for (int mt = 0; mt < 2; mt++) {
                int r = row0 + wm * 32 + mt * 16 + g;
                const float* p = Aext + (size_t)r * 128 + acol + 4 * t;
                bool z0 = (r >= N_NODES);
                bool z1 = (r + 8 >= N_NODES);
                float4 f0 = z0 ? make_float4(0.f, 0.f, 0.f, 0.f) : *(const float4*)p;
                float4 f2 = z0 ? make_float4(0.f, 0.f, 0.f, 0.f) : *(const float4*)(p + 16);
                float4 f1 = z1 ? make_float4(0.f, 0.f, 0.f, 0.f)
                               : *(const float4*)(p + (size_t)8 * 128);
                float4 f3 = z1 ? make_float4(0.f, 0.f, 0.f, 0.f)
                               : *(const float4*)(p + (size_t)8 * 128 + 16);
                ah[mt][0] = pk_e4(f0.x, f0.y, f0.z, f0.w);
                ah[mt][1] = pk_e4(f1.x, f1.y, f1.z, f1.w);
                ah[mt][2] = pk_e4(f2.x, f2.y, f2.z, f2.w);
                ah[mt][3] = pk_e4(f3.x, f3.y, f3.z, f3.w);
            }
        } else {
            const uint32_t* Ab = (ch < 8) ? g_xf8 : g_cf8;
            int base = (ch < 8) ? ch * 8 : (ch - 8) * 8;
            #pragma unroll
            for (int mt = 0; mt < 2; mt++) {
                int r = row0 + wm * 32 + mt * 16 + g;
                const uint32_t* p = Ab + (size_t)r * 64 + base + t;
                ah[mt][0] = p[0];
                ah[mt][1] = p[(size_t)8 * 64];
                ah[mt][2] = p[4];
                ah[mt][3] = p[(size_t)8 * 64 + 4];
            }
        }

        uint2 bh[8];
        const uint2* ph = WF + (size_t)(ch * 32) * 32 + bbase;
        #pragma unroll
        for (int j = 0; j < 8; j++) bh[j] = ph[j * 32];

        #pragma unroll
        for (int mt = 0; mt < 2; mt++)
            #pragma unroll
            for (int j = 0; j < 8; j++)
                mma_f8(acc[mt][j], ah[mt], bh[j].x, bh[j].y);
    }

    __syncthreads();

    const float cs = MODE ? INV_XW : INV_W;

    if (MODE == 1) {
        #pragma unroll
        for (int mt = 0; mt < 2; mt++) {
            float p0 = 0.f, p1 = 0.f;
            #pragma unroll
            for (int j = 0; j < 8; j++) {
                int n0 = wn * 64 + j * 8 + 2 * t;
                float b0 = biasS[n0], b1 = biasS[n0 + 1];
                float v0 = acc[mt][j][0] * cs + b0;
                float v1 = acc[mt][j][1] * cs + b1;
                float v2 = acc[mt][j][2] * cs + b0;
                float v3 = acc[mt][j][3] * cs + b1;
                p0 += v0 * v0 + v1 * v1;
                p1 += v2 * v2 + v3 * v3;
            }
            p0 += __shfl_xor_sync(0xffffffffu, p0, 1);
            p0 += __shfl_xor_sync(0xffffffffu, p0, 2);
            p1 += __shfl_xor_sync(0xffffffffu, p1, 1);
            p1 += __shfl_xor_sync(0xffffffffu, p1, 2);
            if (t == 0) {
                atomicAdd(&ssq[wm * 32 + mt * 16 + g], p0);
                atomicAdd(&ssq[wm * 32 + mt * 16 + 8 + g], p1);
            }
        }
        __syncthreads();
        if (tid < 64) rinv[tid] = 1.0f / fmaxf(sqrtf(ssq[tid]), 1e-12f);
        __syncthreads();
    }

    unsigned short* xf16 = (unsigned short*)g_xf8;

    #pragma unroll
    for (int mt = 0; mt < 2; mt++) {
        int rl = wm * 32 + mt * 16 + g;
        int r = row0 + rl;
        float i0 = (MODE == 1) ? rinv[rl] : 0.f;
        float i1 = (MODE == 1) ? rinv[rl + 8] : 0.f;
        #pragma unroll
        for (int j = 0; j < 8; j++) {
            int n0 = wn * 64 + j * 8 + 2 * t;
            float b0 = biasS[n0], b1 = biasS[n0 + 1];
            float v0 = acc[mt][j][0] * cs + b0;
            float v1 = acc[mt][j][1] * cs + b1;
            float v2 = acc[mt][j][2] * cs + b0;
            float v3 = acc[mt][j][3] * cs + b1;
            size_t u0 = (size_t)r * 128 + n0 / 2;
            size_t u1 = (size_t)(r + 8) * 128 + n0 / 2;
            if (MODE == 0) {
                g_xb[u0] = pk2(v0, v1);
                g_xb[u1] = pk2(v2, v3);
                xf16[u0] = pk_e2(v0 * XSCL, v1 * XSCL);
                xf16[u1] = pk_e2(v2 * XSCL, v3 * XSCL);
            } else {
                uint32_t xw0 = g_xb[u0];
                float o0 = blo(xw0) + fmaxf(v0, 0.f) * i0;
                float o1 = bhi(xw0) + fmaxf(v1, 0.f) * i0;
                g_xb[u0] = pk2(o0, o1);
                xf16[u0] = pk_e2(o0 * XSCL, o1 * XSCL);
                uint32_t xw1 = g_xb[u1];
                float o2 = blo(xw1) + fmaxf(v2, 0.f) * i1;
                float o3 = bhi(xw1) + fmaxf(v3, 0.f) * i1;
                g_xb[u1] = pk2(o2, o3);
                xf16[u1] = pk_e2(o2 * XSCL, o3 * XSCL);
            }
        }
    }
}

// ---------------- graph mean pool (sorted graph_id, run-length fused) ------
__global__ void accum_k(const int* __restrict__ gid) {
    int b = blockIdx.x;
    int c = threadIdx.x;
    int n0 = b * 256;
    int n1 = min(n0 + 256, N_NODES);
    float sum = 0.0f, cnt = 0.0f;
    int cur = gid[n0];
    for (int n = n0; n < n1; n++) {
        int gg = gid[n];
        if (gg != cur) {
            atomicAdd(&g_hg[cur * HID + c], sum);
            if (c == 0) atomicAdd(&g_gcnt[cur], cnt);
            sum = 0.0f; cnt = 0.0f; cur = gg;
        }
        uint32_t w = g_xb[(size_t)n * 128 + (c >> 1)];
        sum += (c & 1) ? bhi(w) : blo(w);
        cnt += 1.0f;
    }
    atomicAdd(&g_hg[cur * HID + c], sum);
    if (c == 0) atomicAdd(&g_gcnt[cur], cnt);
}

__global__ void final_k(const float* __restrict__ p_pos,
                        const float* __restrict__ p_neg,
                        const float* __restrict__ W_fc,
                        float* __restrict__ out) {
    __shared__ float ss[N_GRAPHS][10];
    int t = threadIdx.x;
    if (t < N_GRAPHS * 10) {
        int g = t / 10;
        int p = t % 10;
        const float* P = (p < 5) ? (p_pos + p * HID) : (p_neg + (p - 5) * HID);
        float invc = 1.0f / fmaxf(g_gcnt[g], 1.0f);
        float d = 0.0f;
        for (int c = 0; c < HID; c++) {
            float diff = g_hg[g * HID + c] * invc - P[c];
            d += diff * diff;
        }
        ss[g][p] = logf((d + 1.0f) / (d + 1e-12f));
    }
    __syncthreads();
    if (t < N_GRAPHS) {
        float y = 0.0f;
        #pragma unroll
        for (int j = 0; j < 10; j++) y += ss[t][j] * W_fc[j];
        out[t] = 1.0f / (1.0f + expf(-y));
    }
}

// ---------------- launch ----------------
extern "C" void kernel_launch(void* const* d_in, const int* in_sizes, int n_in,
                              void* d_out, int out_size) {
    const float* h      = (const float*)d_in[0];
    const int*   src    = (const int*)d_in[1];
    const int*   dst    = (const int*)d_in[2];
    const int*   gid    = (const int*)d_in[3];
    const float* W_emb  = (const float*)d_in[4];
    const float* b_emb  = (const float*)d_in[5];
    const float* Ws     = (const float*)d_in[6];
    const float* bs     = (const float*)d_in[7];
    const float* p_pos  = (const float*)d_in[8];
    const float* p_neg  = (const float*)d_in[9];
    const float* W_fc   = (const float*)d_in[10];
    float* out = (float*)d_out;

    prep_k<<<(WF8_U32 + 255) / 256, 256>>>(W_emb, Ws);
    init_k<<<(N_NODES + 255) / 256, 256>>>();
    deg_k<<<(N_EDGES + 255) / 256, 256>>>(dst);
    scanA_k<<<NB, 256>>>();
    scanB_k<<<1, 256>>>();
    scanC_k<<<NB, 256>>>();
    fill_k<<<(N_EDGES + 255) / 256, 256>>>(src, dst);

    tgemm_k<0><<<MT64, 256>>>(h, b_emb, 0);

    for (int l = 0; l < N_LAYERS; l++) {
        agg_k<<<(N_NODES * 32 + 255) / 256, 256>>>();
        tgemm_k<1><<<MT64, 256>>>(nullptr, bs + (size_t)l * HID,
                                  EMB_F8 + l * LYR_F8);
    }

    accum_k<<<NB, 256>>>(gid);
    final_k<<<1, 640>>>(p_pos, p_neg, W_fc, out);
}